// round 1
// baseline (speedup 1.0000x reference)
#include <cuda_runtime.h>
#include <math.h>

#define Bq    4
#define Hh    12
#define Cc    1024
#define Dd    768
#define Ee    30
#define Mm    8
#define Pp    600
#define NL    97
#define RELSn 96
#define EMBn  768
#define NTOT  2400   // B*P
#define LPAD  112    // 97 padded to 28*4

// ---------------- scratch (static device globals; no allocation) -------------
__device__ float g_ent_emb[Bq*Ee*Dd];          // [B,E,D]
__device__ float g_ent_att[Bq*Ee*Hh*Cc];       // [B,E,H,C]
__device__ float g_ht[NTOT*Cc];                // [N,C]
__device__ float g_rs[NTOT*Dd];                // [N,D]
__device__ float g_hz[NTOT*EMBn];              // [N,EMB]
__device__ float g_tz[NTOT*EMBn];              // [N,EMB]
__device__ float g_part[12*NTOT*LPAD];         // k-split partial logits
__device__ float g_riskc[RELSn];

// ---------------- K1: entity embeddings via weighted logsumexp ---------------
__global__ void k_ent_emb(const float* __restrict__ seq,
                          const int* __restrict__ midx,
                          const float* __restrict__ mmask) {
    int be = blockIdx.x;            // b*E + e
    int b  = be / Ee;
    __shared__ int   s_idx[Mm];
    __shared__ float s_w[Mm];
    if (threadIdx.x < Mm) {
        s_idx[threadIdx.x] = midx[be*Mm + threadIdx.x] + 1;   // OFFSET
        s_w[threadIdx.x]   = mmask[be*Mm + threadIdx.x];
    }
    __syncthreads();
    for (int d = threadIdx.x; d < Dd; d += blockDim.x) {
        float xv[Mm];
        float mx = -1e30f;
#pragma unroll
        for (int m = 0; m < Mm; m++) {
            float x = seq[((size_t)b*Cc + s_idx[m])*Dd + d];
            xv[m] = x;
            if (s_w[m] > 0.f) mx = fmaxf(mx, x);
        }
        float s = 0.f;
#pragma unroll
        for (int m = 0; m < Mm; m++)
            if (s_w[m] > 0.f) s += s_w[m] * __expf(xv[m] - mx);
        g_ent_emb[(size_t)be*Dd + d] = __logf(s) + mx;
    }
}

// ---------------- K2: entity attention (mask-weighted mean of rows) ----------
__global__ void k_ent_att(const float* __restrict__ att,
                          const int* __restrict__ midx,
                          const float* __restrict__ mmask) {
    int g  = blockIdx.x;            // ((b*E+e)*H + h)
    int h  = g % Hh;
    int be = g / Hh;
    int b  = be / Ee;
    __shared__ int   s_idx[Mm];
    __shared__ float s_w[Mm];
    if (threadIdx.x < Mm) {
        s_idx[threadIdx.x] = midx[be*Mm + threadIdx.x] + 1;
        s_w[threadIdx.x]   = mmask[be*Mm + threadIdx.x];
    }
    __syncthreads();
    float cnt = 0.f;
#pragma unroll
    for (int m = 0; m < Mm; m++) cnt += s_w[m];
    float inv = 1.f / cnt;
    const float* base = att + ((size_t)b*Hh + h)*Cc*Cc;
    for (int c = threadIdx.x; c < Cc; c += blockDim.x) {
        float s = 0.f;
#pragma unroll
        for (int m = 0; m < Mm; m++)
            s += s_w[m] * base[(size_t)s_idx[m]*Cc + c];
        g_ent_att[(size_t)g*Cc + c] = s * inv;
    }
}

// ---------------- K3: ht_att (head*tail mean over H, normalized) -------------
__global__ void k_ht(const int* __restrict__ hts) {
    int n = blockIdx.x;
    int b = n / Pp;
    int hi = hts[n*2 + 0], ti = hts[n*2 + 1];
    size_t hb = (size_t)(b*Ee + hi) * Hh * Cc;
    size_t tb = (size_t)(b*Ee + ti) * Hh * Cc;
    __shared__ float vals[Cc];
    __shared__ float red[256];
    float loc = 0.f;
    for (int c = threadIdx.x; c < Cc; c += 256) {
        float s = 0.f;
#pragma unroll
        for (int h = 0; h < Hh; h++)
            s += g_ent_att[hb + (size_t)h*Cc + c] * g_ent_att[tb + (size_t)h*Cc + c];
        s *= (1.f / Hh);
        vals[c] = s;
        loc += s;
    }
    red[threadIdx.x] = loc;
    __syncthreads();
    for (int st = 128; st > 0; st >>= 1) {
        if (threadIdx.x < st) red[threadIdx.x] += red[threadIdx.x + st];
        __syncthreads();
    }
    float invt = 1.f / (red[0] + 1e-5f);
    for (int c = threadIdx.x; c < Cc; c += 256)
        g_ht[(size_t)n*Cc + c] = vals[c] * invt;
}

// ---------------- K4: rs = ht_att @ seq  (per-batch GEMM 600x768x1024) -------
__global__ void k_rs(const float* __restrict__ seq) {
    int b  = blockIdx.z;
    int mb = blockIdx.x * 64;   // p tile
    int nb = blockIdx.y * 64;   // d tile
    const float* A  = g_ht + (size_t)b*Pp*Cc;
    const float* Bm = seq + (size_t)b*Cc*Dd;
    __shared__ float As[16][64];
    __shared__ float Bs[16][64];
    int tid = threadIdx.x;
    int tm = tid >> 4, tn = tid & 15;
    int lm = tid & 63, lk4 = (tid >> 6) << 2;
    float acc[4][4] = {};
    for (int kc = 0; kc < Cc; kc += 16) {
        float4 av = make_float4(0.f,0.f,0.f,0.f);
        int p = mb + lm;
        if (p < Pp) av = *(const float4*)&A[(size_t)p*Cc + kc + lk4];
        As[lk4+0][lm] = av.x; As[lk4+1][lm] = av.y;
        As[lk4+2][lm] = av.z; As[lk4+3][lm] = av.w;
#pragma unroll
        for (int r = 0; r < 4; r++) {
            int kk = lk4 + r;
            Bs[kk][lm] = Bm[(size_t)(kc+kk)*Dd + nb + lm];
        }
        __syncthreads();
#pragma unroll
        for (int kk = 0; kk < 16; kk++) {
            float4 a4 = *(const float4*)&As[kk][tm*4];
            float4 b4 = *(const float4*)&Bs[kk][tn*4];
            acc[0][0] += a4.x*b4.x; acc[0][1] += a4.x*b4.y; acc[0][2] += a4.x*b4.z; acc[0][3] += a4.x*b4.w;
            acc[1][0] += a4.y*b4.x; acc[1][1] += a4.y*b4.y; acc[1][2] += a4.y*b4.z; acc[1][3] += a4.y*b4.w;
            acc[2][0] += a4.z*b4.x; acc[2][1] += a4.z*b4.y; acc[2][2] += a4.z*b4.z; acc[2][3] += a4.z*b4.w;
            acc[3][0] += a4.w*b4.x; acc[3][1] += a4.w*b4.y; acc[3][2] += a4.w*b4.z; acc[3][3] += a4.w*b4.w;
        }
        __syncthreads();
    }
#pragma unroll
    for (int a = 0; a < 4; a++) {
        int p = mb + tm*4 + a;
        if (p < Pp) {
            float4 v = make_float4(acc[a][0], acc[a][1], acc[a][2], acc[a][3]);
            *(float4*)&g_rs[((size_t)(b*Pp + p))*Dd + nb + tn*4] = v;
        }
    }
}

// ---------------- K5: hz/tz = tanh([gather(ent) , rs] @ W + b) ---------------
__global__ void k_headtail(const float* __restrict__ W, const float* __restrict__ bias,
                           const int* __restrict__ hts, int col) {
    float* outz = (col == 0) ? g_hz : g_tz;
    int mb = blockIdx.x * 64;
    int nb = blockIdx.y * 64;
    __shared__ float As[16][64];
    __shared__ float Bs[16][64];
    __shared__ long  aoff[64];
    int tid = threadIdx.x;
    if (tid < 64) {
        int n = mb + tid;
        long off = -1;
        if (n < NTOT) {
            int b = n / Pp, p = n % Pp;
            int ei = hts[(size_t)(b*Pp + p)*2 + col];
            off = (long)(b*Ee + ei) * Dd;
        }
        aoff[tid] = off;
    }
    __syncthreads();
    int tm = tid >> 4, tn = tid & 15;
    int lm = tid & 63, lk4 = (tid >> 6) << 2;
    float acc[4][4] = {};
    for (int kc = 0; kc < 2*Dd; kc += 16) {
        float4 av = make_float4(0.f,0.f,0.f,0.f);
        long off = aoff[lm];
        if (off >= 0) {
            if (kc < Dd) av = *(const float4*)&g_ent_emb[off + kc + lk4];
            else         av = *(const float4*)&g_rs[(size_t)(mb+lm)*Dd + (kc - Dd) + lk4];
        }
        As[lk4+0][lm] = av.x; As[lk4+1][lm] = av.y;
        As[lk4+2][lm] = av.z; As[lk4+3][lm] = av.w;
#pragma unroll
        for (int r = 0; r < 4; r++) {
            int kk = lk4 + r;
            Bs[kk][lm] = W[(size_t)(kc+kk)*EMBn + nb + lm];
        }
        __syncthreads();
#pragma unroll
        for (int kk = 0; kk < 16; kk++) {
            float4 a4 = *(const float4*)&As[kk][tm*4];
            float4 b4 = *(const float4*)&Bs[kk][tn*4];
            acc[0][0] += a4.x*b4.x; acc[0][1] += a4.x*b4.y; acc[0][2] += a4.x*b4.z; acc[0][3] += a4.x*b4.w;
            acc[1][0] += a4.y*b4.x; acc[1][1] += a4.y*b4.y; acc[1][2] += a4.y*b4.z; acc[1][3] += a4.y*b4.w;
            acc[2][0] += a4.z*b4.x; acc[2][1] += a4.z*b4.y; acc[2][2] += a4.z*b4.z; acc[2][3] += a4.z*b4.w;
            acc[3][0] += a4.w*b4.x; acc[3][1] += a4.w*b4.y; acc[3][2] += a4.w*b4.z; acc[3][3] += a4.w*b4.w;
        }
        __syncthreads();
    }
#pragma unroll
    for (int a = 0; a < 4; a++) {
        int n = mb + tm*4 + a;
        if (n < NTOT) {
            int cb = nb + tn*4;
            float4 v;
            v.x = tanhf(acc[a][0] + bias[cb+0]);
            v.y = tanhf(acc[a][1] + bias[cb+1]);
            v.z = tanhf(acc[a][2] + bias[cb+2]);
            v.w = tanhf(acc[a][3] + bias[cb+3]);
            *(float4*)&outz[(size_t)n*EMBn + cb] = v;
        }
    }
}

// ---------------- K6: block-bilinear implicit GEMM (k-split partials) --------
// logits[n,l] = sum_{k,i,j} hz[n,64k+i]*tz[n,64k+j]*W[(k*4096+i*64+j), l]
// Tile: 32 n x 112 l x (one k = 4096 r). 224 threads, frag 4n x 4l.
__global__ __launch_bounds__(224) void k_bilin(const float* __restrict__ Wb) {
    int nB = blockIdx.x * 32;
    int k  = blockIdx.y;
    __shared__ float hzs[64][32];
    __shared__ float tzs[64][32];
    __shared__ float Ws[64][LPAD];
    int tid = threadIdx.x;
    for (int e = tid; e < 64*32; e += 224) {
        int i = e >> 5, nn = e & 31;
        size_t src = (size_t)(nB + nn)*EMBn + k*64 + i;
        hzs[i][nn] = g_hz[src];
        tzs[i][nn] = g_tz[src];
    }
    int tn = tid / 28, tl = tid % 28;   // tn:0..7 (x4 n), tl:0..27 (x4 l)
    float acc[4][4] = {};
    for (int i = 0; i < 64; i++) {
        __syncthreads();
        for (int e = tid; e < 64*LPAD; e += 224) {
            int j = e / LPAD, l = e % LPAD;
            Ws[j][l] = (l < NL) ? Wb[(size_t)((k*64 + i)*64 + j)*NL + l] : 0.f;
        }
        __syncthreads();
        float4 an = *(const float4*)&hzs[i][tn*4];
#pragma unroll 8
        for (int j = 0; j < 64; j++) {
            float4 t4 = *(const float4*)&tzs[j][tn*4];
            float4 w4 = *(const float4*)&Ws[j][tl*4];
            float av0 = an.x*t4.x, av1 = an.y*t4.y, av2 = an.z*t4.z, av3 = an.w*t4.w;
            acc[0][0] += av0*w4.x; acc[0][1] += av0*w4.y; acc[0][2] += av0*w4.z; acc[0][3] += av0*w4.w;
            acc[1][0] += av1*w4.x; acc[1][1] += av1*w4.y; acc[1][2] += av1*w4.z; acc[1][3] += av1*w4.w;
            acc[2][0] += av2*w4.x; acc[2][1] += av2*w4.y; acc[2][2] += av2*w4.z; acc[2][3] += av2*w4.w;
            acc[3][0] += av3*w4.x; acc[3][1] += av3*w4.y; acc[3][2] += av3*w4.z; acc[3][3] += av3*w4.w;
        }
    }
#pragma unroll
    for (int a = 0; a < 4; a++) {
        int n = nB + tn*4 + a;
        *(float4*)&g_part[((size_t)k*NTOT + n)*LPAD + tl*4] =
            make_float4(acc[a][0], acc[a][1], acc[a][2], acc[a][3]);
    }
}

// ---------------- K6b: reduce k-partials + bias -> logits in d_out -----------
__global__ void k_logits(const float* __restrict__ bb, float* __restrict__ out) {
    int g = blockIdx.x * 256 + threadIdx.x;
    if (g >= NTOT*NL) return;
    int n = g / NL, l = g % NL;
    float s = bb[l];
#pragma unroll
    for (int k = 0; k < 12; k++)
        s += g_part[((size_t)k*NTOT + n)*LPAD + l];
    out[1 + (size_t)n*NL + l] = s;
}

// ---------------- K7: per-class S-PU risk -------------------------------------
__global__ void k_risk(const float* __restrict__ out, const int* __restrict__ labels,
                       const float* __restrict__ pl, const float* __restrict__ po) {
    int r = blockIdx.x;   // 0..95
    int tid = threadIdx.x;
    float s_neg = 0.f, s_pp = 0.f, s_pn = 0.f, c_pos = 0.f;
    for (int n = tid; n < NTOT; n += 256) {
        float l0 = out[1 + (size_t)n*NL];
        float sc = out[1 + (size_t)n*NL + (r+1)] - l0;
        bool pos = labels[(size_t)n*NL + (r+1)] == 1;
        float lp = 0.25f * (sc - 1.f) * (sc - 1.f);
        float ln = 0.25f * (-sc - 1.f) * (-sc - 1.f);
        if (pos) { c_pos += 1.f; s_pp += lp; s_pn += ln; }
        else     { s_neg += ln; }
    }
    __shared__ float red[4][256];
    red[0][tid] = s_neg; red[1][tid] = s_pp; red[2][tid] = s_pn; red[3][tid] = c_pos;
    __syncthreads();
    for (int st = 128; st > 0; st >>= 1) {
        if (tid < st) {
#pragma unroll
            for (int q = 0; q < 4; q++) red[q][tid] += red[q][tid + st];
        }
        __syncthreads();
    }
    if (tid == 0) {
        float cp = red[3][0], cn = (float)NTOT - cp;
        float sq_neg = (cn > 0.f) ? red[0][0] / fmaxf(cn, 1.f) : 0.f;
        float sq_pp  = (cp > 0.f) ? red[1][0] / fmaxf(cp, 1.f) : 0.f;
        float sq_pn  = (cp > 0.f) ? red[2][0] / fmaxf(cp, 1.f) : 0.f;
        float o = po[r], lq = pl[r];
        float w  = sqrtf((1.f - o) / o);
        float pu = (o - lq) / (1.f - lq);
        float risk1 = (1.f - o)/(1.f - pu)*sq_neg - (pu - pu*o)/(1.f - pu)*sq_pn;
        float risk2 = o * sq_pp * w;
        g_riskc[r] = (risk1 < 0.f) ? -risk1 : (risk1 + risk2);
    }
}

// ---------------- K8: sum class risks -> out[0] -------------------------------
__global__ void k_risk_sum(float* __restrict__ out) {
    __shared__ float rr[128];
    int t = threadIdx.x;
    rr[t] = (t < RELSn) ? g_riskc[t] : 0.f;
    __syncthreads();
    for (int st = 64; st > 0; st >>= 1) {
        if (t < st) rr[t] += rr[t + st];
        __syncthreads();
    }
    if (t == 0) out[0] = rr[0];
}

// ---------------- launch -------------------------------------------------------
extern "C" void kernel_launch(void* const* d_in, const int* in_sizes, int n_in,
                              void* d_out, int out_size) {
    const float* seq      = (const float*)d_in[0];
    const float* att      = (const float*)d_in[1];
    const int*   midx     = (const int*)  d_in[2];
    const float* mmask    = (const float*)d_in[3];
    const int*   hts      = (const int*)  d_in[4];
    const int*   labels   = (const int*)  d_in[5];
    const float* priors_l = (const float*)d_in[6];
    const float* priors_o = (const float*)d_in[7];
    const float* head_W   = (const float*)d_in[8];
    const float* head_b   = (const float*)d_in[9];
    const float* tail_W   = (const float*)d_in[10];
    const float* tail_b   = (const float*)d_in[11];
    const float* bil_W    = (const float*)d_in[12];
    const float* bil_b    = (const float*)d_in[13];
    float* out = (float*)d_out;

    k_ent_emb<<<Bq*Ee, 256>>>(seq, midx, mmask);
    k_ent_att<<<Bq*Ee*Hh, 256>>>(att, midx, mmask);
    k_ht<<<NTOT, 256>>>(hts);
    k_rs<<<dim3(10, 12, 4), 256>>>(seq);
    k_headtail<<<dim3(38, 12), 256>>>(head_W, head_b, hts, 0);
    k_headtail<<<dim3(38, 12), 256>>>(tail_W, tail_b, hts, 1);
    k_bilin<<<dim3(75, 12), 224>>>(bil_W);
    k_logits<<<(NTOT*NL + 255)/256, 256>>>(bil_b, out);
    k_risk<<<RELSn, 256>>>(out, labels, priors_l, priors_o);
    k_risk_sum<<<1, 128>>>(out);
}

// round 3
// speedup vs baseline: 1.4582x; 1.4582x over previous
#include <cuda_runtime.h>
#include <cuda_bf16.h>
#include <math.h>
#include <stdint.h>

#define Bq    4
#define Hh    12
#define Cc    1024
#define Dd    768
#define Ee    30
#define Mm    8
#define Pp    600
#define NL    97
#define RELSn 96
#define EMBn  768
#define NTOT  2400   // B*P
#define NPAD  2560   // 20 tiles of 128 (rows >= NTOT stay zero)
#define NSPLIT 24    // 12 k * 2 i-halves

// ---------------- scratch (static device globals; no allocation) -------------
__device__ float g_ent_emb[Bq*Ee*Dd];          // [B,E,D]
__device__ float g_ent_att[Bq*Ee*Hh*Cc];       // [B,E,H,C]
__device__ float g_ht[NTOT*Cc];                // [N,C]
__device__ float g_rs[NTOT*Dd];                // [N,D]
__device__ float g_hz[NPAD*EMBn];              // [Npad,EMB] (rows >=2400 stay zero)
__device__ float g_tz[NPAD*EMBn];
__device__ uint32_t g_wt_hi[768*4096];         // per blob(k,i): [64 j][64 lpair] bf16x2
__device__ uint32_t g_wt_lo[768*4096];
__device__ float g_part[NSPLIT*NPAD*128];      // split partial logits
__device__ float g_riskc[RELSn];

// =================== helpers ===================================================
__device__ __forceinline__ uint32_t smem_u32(const void* p) {
    uint32_t a;
    asm("{ .reg .u64 t; cvta.to.shared.u64 t, %1; cvt.u32.u64 %0, t; }" : "=r"(a) : "l"(p));
    return a;
}
// split (p0,p1) fp32 -> bf16x2 hi pack + bf16x2 lo (residual) pack
__device__ __forceinline__ void pack2(float p0, float p1, uint32_t& hi, uint32_t& lo) {
    uint32_t h;
    asm("cvt.rn.bf16x2.f32 %0, %1, %2;" : "=r"(h) : "f"(p1), "f"(p0));
    float h0 = __uint_as_float(h << 16);
    float h1 = __uint_as_float(h & 0xFFFF0000u);
    float l0 = p0 - h0, l1 = p1 - h1;
    uint32_t l;
    asm("cvt.rn.bf16x2.f32 %0, %1, %2;" : "=r"(l) : "f"(l1), "f"(l0));
    hi = h; lo = l;
}
__device__ __forceinline__ void ldm_x4(uint32_t* r, uint32_t addr) {
    asm volatile("ldmatrix.sync.aligned.m8n8.x4.shared.b16 {%0,%1,%2,%3}, [%4];"
        : "=r"(r[0]), "=r"(r[1]), "=r"(r[2]), "=r"(r[3]) : "r"(addr));
}
__device__ __forceinline__ void ldm_x4_t(uint32_t* r, uint32_t addr) {
    asm volatile("ldmatrix.sync.aligned.m8n8.x4.trans.shared.b16 {%0,%1,%2,%3}, [%4];"
        : "=r"(r[0]), "=r"(r[1]), "=r"(r[2]), "=r"(r[3]) : "r"(addr));
}
__device__ __forceinline__ void mma_bf16(float* d, const uint32_t* a, const uint32_t* b) {
    asm volatile(
        "mma.sync.aligned.m16n8k16.row.col.f32.bf16.bf16.f32 "
        "{%0,%1,%2,%3}, {%4,%5,%6,%7}, {%8,%9}, {%0,%1,%2,%3};"
        : "+f"(d[0]), "+f"(d[1]), "+f"(d[2]), "+f"(d[3])
        : "r"(a[0]), "r"(a[1]), "r"(a[2]), "r"(a[3]), "r"(b[0]), "r"(b[1]));
}

// ---------------- K1: entity embeddings via weighted logsumexp ---------------
__global__ void k_ent_emb(const float* __restrict__ seq,
                          const int* __restrict__ midx,
                          const float* __restrict__ mmask) {
    int be = blockIdx.x;
    int b  = be / Ee;
    __shared__ int   s_idx[Mm];
    __shared__ float s_w[Mm];
    if (threadIdx.x < Mm) {
        s_idx[threadIdx.x] = midx[be*Mm + threadIdx.x] + 1;
        s_w[threadIdx.x]   = mmask[be*Mm + threadIdx.x];
    }
    __syncthreads();
    for (int d = threadIdx.x; d < Dd; d += blockDim.x) {
        float xv[Mm];
        float mx = -1e30f;
#pragma unroll
        for (int m = 0; m < Mm; m++) {
            float x = seq[((size_t)b*Cc + s_idx[m])*Dd + d];
            xv[m] = x;
            if (s_w[m] > 0.f) mx = fmaxf(mx, x);
        }
        float s = 0.f;
#pragma unroll
        for (int m = 0; m < Mm; m++)
            if (s_w[m] > 0.f) s += s_w[m] * __expf(xv[m] - mx);
        g_ent_emb[(size_t)be*Dd + d] = __logf(s) + mx;
    }
}

// ---------------- K2: entity attention (mask-weighted mean of rows) ----------
__global__ void k_ent_att(const float* __restrict__ att,
                          const int* __restrict__ midx,
                          const float* __restrict__ mmask) {
    int g  = blockIdx.x;
    int h  = g % Hh;
    int be = g / Hh;
    int b  = be / Ee;
    __shared__ int   s_idx[Mm];
    __shared__ float s_w[Mm];
    if (threadIdx.x < Mm) {
        s_idx[threadIdx.x] = midx[be*Mm + threadIdx.x] + 1;
        s_w[threadIdx.x]   = mmask[be*Mm + threadIdx.x];
    }
    __syncthreads();
    float cnt = 0.f;
#pragma unroll
    for (int m = 0; m < Mm; m++) cnt += s_w[m];
    float inv = 1.f / cnt;
    const float* base = att + ((size_t)b*Hh + h)*Cc*Cc;
    for (int c = threadIdx.x; c < Cc; c += blockDim.x) {
        float s = 0.f;
#pragma unroll
        for (int m = 0; m < Mm; m++)
            s += s_w[m] * base[(size_t)s_idx[m]*Cc + c];
        g_ent_att[(size_t)g*Cc + c] = s * inv;
    }
}

// ---------------- K3: ht_att (head*tail mean over H, normalized) -------------
__global__ void k_ht(const int* __restrict__ hts) {
    int n = blockIdx.x;
    int b = n / Pp;
    int hi = hts[n*2 + 0], ti = hts[n*2 + 1];
    size_t hb = (size_t)(b*Ee + hi) * Hh * Cc;
    size_t tb = (size_t)(b*Ee + ti) * Hh * Cc;
    __shared__ float vals[Cc];
    __shared__ float red[256];
    float loc = 0.f;
    for (int c = threadIdx.x; c < Cc; c += 256) {
        float s = 0.f;
#pragma unroll
        for (int h = 0; h < Hh; h++)
            s += g_ent_att[hb + (size_t)h*Cc + c] * g_ent_att[tb + (size_t)h*Cc + c];
        s *= (1.f / Hh);
        vals[c] = s;
        loc += s;
    }
    red[threadIdx.x] = loc;
    __syncthreads();
    for (int st = 128; st > 0; st >>= 1) {
        if (threadIdx.x < st) red[threadIdx.x] += red[threadIdx.x + st];
        __syncthreads();
    }
    float invt = 1.f / (red[0] + 1e-5f);
    for (int c = threadIdx.x; c < Cc; c += 256)
        g_ht[(size_t)n*Cc + c] = vals[c] * invt;
}

// ---------------- K4: rs = ht_att @ seq  (per-batch GEMM 600x768x1024) -------
__global__ void k_rs(const float* __restrict__ seq) {
    int b  = blockIdx.z;
    int mb = blockIdx.x * 64;
    int nb = blockIdx.y * 64;
    const float* A  = g_ht + (size_t)b*Pp*Cc;
    const float* Bm = seq + (size_t)b*Cc*Dd;
    __shared__ float As[16][64];
    __shared__ float Bs[16][64];
    int tid = threadIdx.x;
    int tm = tid >> 4, tn = tid & 15;
    int lm = tid & 63, lk4 = (tid >> 6) << 2;
    float acc[4][4] = {};
    for (int kc = 0; kc < Cc; kc += 16) {
        float4 av = make_float4(0.f,0.f,0.f,0.f);
        int p = mb + lm;
        if (p < Pp) av = *(const float4*)&A[(size_t)p*Cc + kc + lk4];
        As[lk4+0][lm] = av.x; As[lk4+1][lm] = av.y;
        As[lk4+2][lm] = av.z; As[lk4+3][lm] = av.w;
#pragma unroll
        for (int r = 0; r < 4; r++) {
            int kk = lk4 + r;
            Bs[kk][lm] = Bm[(size_t)(kc+kk)*Dd + nb + lm];
        }
        __syncthreads();
#pragma unroll
        for (int kk = 0; kk < 16; kk++) {
            float4 a4 = *(const float4*)&As[kk][tm*4];
            float4 b4 = *(const float4*)&Bs[kk][tn*4];
            acc[0][0] += a4.x*b4.x; acc[0][1] += a4.x*b4.y; acc[0][2] += a4.x*b4.z; acc[0][3] += a4.x*b4.w;
            acc[1][0] += a4.y*b4.x; acc[1][1] += a4.y*b4.y; acc[1][2] += a4.y*b4.z; acc[1][3] += a4.y*b4.w;
            acc[2][0] += a4.z*b4.x; acc[2][1] += a4.z*b4.y; acc[2][2] += a4.z*b4.z; acc[2][3] += a4.z*b4.w;
            acc[3][0] += a4.w*b4.x; acc[3][1] += a4.w*b4.y; acc[3][2] += a4.w*b4.z; acc[3][3] += a4.w*b4.w;
        }
        __syncthreads();
    }
#pragma unroll
    for (int a = 0; a < 4; a++) {
        int p = mb + tm*4 + a;
        if (p < Pp) {
            float4 v = make_float4(acc[a][0], acc[a][1], acc[a][2], acc[a][3]);
            *(float4*)&g_rs[((size_t)(b*Pp + p))*Dd + nb + tn*4] = v;
        }
    }
}

// ---------------- K5: hz/tz = tanh([gather(ent) , rs] @ W + b) ---------------
__global__ void k_headtail(const float* __restrict__ W, const float* __restrict__ bias,
                           const int* __restrict__ hts, int col) {
    float* outz = (col == 0) ? g_hz : g_tz;
    int mb = blockIdx.x * 64;
    int nb = blockIdx.y * 64;
    __shared__ float As[16][64];
    __shared__ float Bs[16][64];
    __shared__ long  aoff[64];
    int tid = threadIdx.x;
    if (tid < 64) {
        int n = mb + tid;
        long off = -1;
        if (n < NTOT) {
            int b = n / Pp, p = n % Pp;
            int ei = hts[(size_t)(b*Pp + p)*2 + col];
            off = (long)(b*Ee + ei) * Dd;
        }
        aoff[tid] = off;
    }
    __syncthreads();
    int tm = tid >> 4, tn = tid & 15;
    int lm = tid & 63, lk4 = (tid >> 6) << 2;
    float acc[4][4] = {};
    for (int kc = 0; kc < 2*Dd; kc += 16) {
        float4 av = make_float4(0.f,0.f,0.f,0.f);
        long off = aoff[lm];
        if (off >= 0) {
            if (kc < Dd) av = *(const float4*)&g_ent_emb[off + kc + lk4];
            else         av = *(const float4*)&g_rs[(size_t)(mb+lm)*Dd + (kc - Dd) + lk4];
        }
        As[lk4+0][lm] = av.x; As[lk4+1][lm] = av.y;
        As[lk4+2][lm] = av.z; As[lk4+3][lm] = av.w;
#pragma unroll
        for (int r = 0; r < 4; r++) {
            int kk = lk4 + r;
            Bs[kk][lm] = W[(size_t)(kc+kk)*EMBn + nb + lm];
        }
        __syncthreads();
#pragma unroll
        for (int kk = 0; kk < 16; kk++) {
            float4 a4 = *(const float4*)&As[kk][tm*4];
            float4 b4 = *(const float4*)&Bs[kk][tn*4];
            acc[0][0] += a4.x*b4.x; acc[0][1] += a4.x*b4.y; acc[0][2] += a4.x*b4.z; acc[0][3] += a4.x*b4.w;
            acc[1][0] += a4.y*b4.x; acc[1][1] += a4.y*b4.y; acc[1][2] += a4.y*b4.z; acc[1][3] += a4.y*b4.w;
            acc[2][0] += a4.z*b4.x; acc[2][1] += a4.z*b4.y; acc[2][2] += a4.z*b4.z; acc[2][3] += a4.z*b4.w;
            acc[3][0] += a4.w*b4.x; acc[3][1] += a4.w*b4.y; acc[3][2] += a4.w*b4.z; acc[3][3] += a4.w*b4.w;
        }
        __syncthreads();
    }
#pragma unroll
    for (int a = 0; a < 4; a++) {
        int n = mb + tm*4 + a;
        if (n < NTOT) {
            int cb = nb + tn*4;
            float4 v;
            v.x = tanhf(acc[a][0] + bias[cb+0]);
            v.y = tanhf(acc[a][1] + bias[cb+1]);
            v.z = tanhf(acc[a][2] + bias[cb+2]);
            v.w = tanhf(acc[a][3] + bias[cb+3]);
            *(float4*)&outz[(size_t)n*EMBn + cb] = v;
        }
    }
}

// ---------------- K6a: pre-split bil_W into hi/lo bf16 B-tiles -----------------
// g_wt[blob=(k*64+i)][j 0..63][lpair 0..63] : bf16x2 over l (l>=97 zero)
__global__ void k_wsplit(const float* __restrict__ W) {
    int blob = blockIdx.x;               // 0..767
    int t = threadIdx.x;                 // 256
    int j = t >> 2, lq = (t & 3) * 32;   // each thread: 32 l values
    size_t row = ((size_t)blob*64 + j) * NL;
    uint32_t* oh = g_wt_hi + ((size_t)blob*64 + j)*64 + lq/2;
    uint32_t* ol = g_wt_lo + ((size_t)blob*64 + j)*64 + lq/2;
#pragma unroll
    for (int q = 0; q < 16; q++) {
        int l0 = lq + q*2, l1 = l0 + 1;
        float v0 = (l0 < NL) ? W[row + l0] : 0.f;
        float v1 = (l1 < NL) ? W[row + l1] : 0.f;
        uint32_t h, l;
        pack2(v0, v1, h, l);
        oh[q] = h; ol[q] = l;
    }
}

// ---------------- K6b: mma.sync block-bilinear (bf16x3, split partials) -------
// CTA: 128 n x 128 l x (k, ihalf); K-loop = 32 i-steps, each K=64 (j).
// smem: TZ fp32 [128][64] | A hi/lo [128][72 bf16] | B hi/lo [64][136 bf16]
#define SM_TZ 0
#define SM_AH 32768
#define SM_AL 51200
#define SM_BH 69632
#define SM_BL 87040
#define SM_TOT 104448

__global__ __launch_bounds__(256, 2) void k_bilin_mma() {
    extern __shared__ char sm[];
    float* TZ = (float*)(sm + SM_TZ);
    uint32_t smb = smem_u32(sm);
    int tid = threadIdx.x, lane = tid & 31, wid = tid >> 5;
    int n0 = blockIdx.x * 128, k = blockIdx.y, ih = blockIdx.z;

    // cache tz tile fp32 in smem
    for (int idx = tid; idx < 2048; idx += 256) {
        int r = idx >> 4, c = (idx & 15) * 4;
        *(float4*)&TZ[r*64 + c] = *(const float4*)&g_tz[(size_t)(n0 + r)*EMBn + k*64 + c];
    }
    // A-gen mapping
    int anl = tid >> 1, ajh = tid & 1;
    const float* hzp = g_hz + (size_t)(n0 + anl)*EMBn + k*64 + ih*32;
    // mma mapping: warp tile 64n x 32l
    int wn = wid >> 2, wl = wid & 3;
    int lq  = lane & 15, lh = lane >> 4;
    uint32_t a_base = smb + SM_AH + (wn*64 + lq)*144 + lh*16;        // + mt*16*144 + kt*32
    uint32_t al_base = a_base + (SM_AL - SM_AH);
    uint32_t b_base = smb + SM_BH + lq*272 + (wl*64 + lh*16);        // + kt*16*272 + lt*32
    uint32_t bl_base = b_base + (SM_BL - SM_BH);

    float acc[4][4][4] = {};
    __syncthreads();

    for (int is = 0; is < 32; is++) {
        int i = ih*32 + is;
        // ---- stage B tile (hi/lo) into padded smem
        size_t blob4 = ((size_t)(k*64 + i)) * 1024;   // uint4 units
        const uint4* wh = reinterpret_cast<const uint4*>(g_wt_hi);
        const uint4* wlo = reinterpret_cast<const uint4*>(g_wt_lo);
#pragma unroll
        for (int rep = 0; rep < 4; rep++) {
            int idx = tid + rep*256;
            int j = idx >> 4, c = idx & 15;
            *(uint4*)(sm + SM_BH + j*272 + c*16) = wh[blob4 + idx];
            *(uint4*)(sm + SM_BL + j*272 + c*16) = wlo[blob4 + idx];
        }
        // ---- stage A = hz[:,i] (x) tz, split hi/lo
        float hzv = hzp[is];
        const float* tzr = &TZ[anl*64 + ajh*32];
        char* ah = sm + SM_AH + anl*144 + ajh*64;
        char* al = sm + SM_AL + anl*144 + ajh*64;
#pragma unroll
        for (int g = 0; g < 4; g++) {
            float4 t0 = *(const float4*)&tzr[g*8];
            float4 t1 = *(const float4*)&tzr[g*8 + 4];
            uint32_t h[4], l[4];
            pack2(hzv*t0.x, hzv*t0.y, h[0], l[0]);
            pack2(hzv*t0.z, hzv*t0.w, h[1], l[1]);
            pack2(hzv*t1.x, hzv*t1.y, h[2], l[2]);
            pack2(hzv*t1.z, hzv*t1.w, h[3], l[3]);
            *(uint4*)(ah + g*16) = make_uint4(h[0], h[1], h[2], h[3]);
            *(uint4*)(al + g*16) = make_uint4(l[0], l[1], l[2], l[3]);
        }
        __syncthreads();
        // ---- mma over K=64 (4 k-tiles of 16)
#pragma unroll
        for (int kt = 0; kt < 4; kt++) {
            uint32_t a_hi[4][4], a_lo[4][4];
#pragma unroll
            for (int mt = 0; mt < 4; mt++) {
                ldm_x4(a_hi[mt], a_base  + mt*(16*144) + kt*32);
                ldm_x4(a_lo[mt], al_base + mt*(16*144) + kt*32);
            }
#pragma unroll
            for (int lt = 0; lt < 2; lt++) {
                uint32_t b_hi[4], b_lo[4];
                ldm_x4_t(b_hi, b_base  + kt*(16*272) + lt*32);
                ldm_x4_t(b_lo, bl_base + kt*(16*272) + lt*32);
#pragma unroll
                for (int mt = 0; mt < 4; mt++) {
#pragma unroll
                    for (int f = 0; f < 2; f++) {
                        float* d = acc[mt][lt*2 + f];
                        mma_bf16(d, a_hi[mt], &b_hi[f*2]);
                        mma_bf16(d, a_lo[mt], &b_hi[f*2]);
                        mma_bf16(d, a_hi[mt], &b_lo[f*2]);
                    }
                }
            }
        }
        __syncthreads();
    }
    // ---- epilogue: write split partials
    int split = k*2 + ih;
    int rbase = n0 + wn*64 + (lane >> 2);
    int cbase = wl*32 + (lane & 3)*2;
#pragma unroll
    for (int mt = 0; mt < 4; mt++) {
#pragma unroll
        for (int lf = 0; lf < 4; lf++) {
            int r = rbase + mt*16;
            int c = cbase + lf*8;
            float* d = acc[mt][lf];
            *(float2*)&g_part[((size_t)split*NPAD + r)*128 + c]     = make_float2(d[0], d[1]);
            *(float2*)&g_part[((size_t)split*NPAD + r + 8)*128 + c] = make_float2(d[2], d[3]);
        }
    }
}

// ---------------- K6c: reduce split partials + bias -> logits -----------------
__global__ void k_logits(const float* __restrict__ bb, float* __restrict__ out) {
    int g = blockIdx.x * 256 + threadIdx.x;
    if (g >= NTOT*NL) return;
    int n = g / NL, l = g % NL;
    float s = bb[l];
#pragma unroll
    for (int sp = 0; sp < NSPLIT; sp++)
        s += g_part[((size_t)sp*NPAD + n)*128 + l];
    out[1 + (size_t)n*NL + l] = s;
}

// ---------------- K7: per-class S-PU risk -------------------------------------
__global__ void k_risk(const float* __restrict__ out, const int* __restrict__ labels,
                       const float* __restrict__ pl, const float* __restrict__ po) {
    int r = blockIdx.x;
    int tid = threadIdx.x;
    float s_neg = 0.f, s_pp = 0.f, s_pn = 0.f, c_pos = 0.f;
    for (int n = tid; n < NTOT; n += 256) {
        float l0 = out[1 + (size_t)n*NL];
        float sc = out[1 + (size_t)n*NL + (r+1)] - l0;
        bool pos = labels[(size_t)n*NL + (r+1)] == 1;
        float lp = 0.25f * (sc - 1.f) * (sc - 1.f);
        float ln = 0.25f * (-sc - 1.f) * (-sc - 1.f);
        if (pos) { c_pos += 1.f; s_pp += lp; s_pn += ln; }
        else     { s_neg += ln; }
    }
    __shared__ float red[4][256];
    red[0][tid] = s_neg; red[1][tid] = s_pp; red[2][tid] = s_pn; red[3][tid] = c_pos;
    __syncthreads();
    for (int st = 128; st > 0; st >>= 1) {
        if (tid < st) {
#pragma unroll
            for (int q = 0; q < 4; q++) red[q][tid] += red[q][tid + st];
        }
        __syncthreads();
    }
    if (tid == 0) {
        float cp = red[3][0], cn = (float)NTOT - cp;
        float sq_neg = (cn > 0.f) ? red[0][0] / fmaxf(cn, 1.f) : 0.f;
        float sq_pp  = (cp > 0.f) ? red[1][0] / fmaxf(cp, 1.f) : 0.f;
        float sq_pn  = (cp > 0.f) ? red[2][0] / fmaxf(cp, 1.f) : 0.f;
        float o = po[r], lq = pl[r];
        float w  = sqrtf((1.f - o) / o);
        float pu = (o - lq) / (1.f - lq);
        float risk1 = (1.f - o)/(1.f - pu)*sq_neg - (pu - pu*o)/(1.f - pu)*sq_pn;
        float risk2 = o * sq_pp * w;
        g_riskc[r] = (risk1 < 0.f) ? -risk1 : (risk1 + risk2);
    }
}

// ---------------- K8: sum class risks -> out[0] -------------------------------
__global__ void k_risk_sum(float* __restrict__ out) {
    __shared__ float rr[128];
    int t = threadIdx.x;
    rr[t] = (t < RELSn) ? g_riskc[t] : 0.f;
    __syncthreads();
    for (int st = 64; st > 0; st >>= 1) {
        if (t < st) rr[t] += rr[t + st];
        __syncthreads();
    }
    if (t == 0) out[0] = rr[0];
}

// ---------------- launch -------------------------------------------------------
extern "C" void kernel_launch(void* const* d_in, const int* in_sizes, int n_in,
                              void* d_out, int out_size) {
    const float* seq      = (const float*)d_in[0];
    const float* att      = (const float*)d_in[1];
    const int*   midx     = (const int*)  d_in[2];
    const float* mmask    = (const float*)d_in[3];
    const int*   hts      = (const int*)  d_in[4];
    const int*   labels   = (const int*)  d_in[5];
    const float* priors_l = (const float*)d_in[6];
    const float* priors_o = (const float*)d_in[7];
    const float* head_W   = (const float*)d_in[8];
    const float* head_b   = (const float*)d_in[9];
    const float* tail_W   = (const float*)d_in[10];
    const float* tail_b   = (const float*)d_in[11];
    const float* bil_W    = (const float*)d_in[12];
    const float* bil_b    = (const float*)d_in[13];
    float* out = (float*)d_out;

    static int smem_set = 0;
    if (!smem_set) {
        cudaFuncSetAttribute(k_bilin_mma, cudaFuncAttributeMaxDynamicSharedMemorySize, SM_TOT);
        smem_set = 1;
    }

    k_wsplit<<<768, 256>>>(bil_W);
    k_ent_emb<<<Bq*Ee, 256>>>(seq, midx, mmask);
    k_ent_att<<<Bq*Ee*Hh, 256>>>(att, midx, mmask);
    k_ht<<<NTOT, 256>>>(hts);
    k_rs<<<dim3(10, 12, 4), 256>>>(seq);
    k_headtail<<<dim3(38, 12), 256>>>(head_W, head_b, hts, 0);
    k_headtail<<<dim3(38, 12), 256>>>(tail_W, tail_b, hts, 1);
    k_bilin_mma<<<dim3(20, 12, 2), 256, SM_TOT>>>();
    k_logits<<<(NTOT*NL + 255)/256, 256>>>(bil_b, out);
    k_risk<<<RELSn, 256>>>(out, labels, priors_l, priors_o);
    k_risk_sum<<<1, 128>>>(out);
}

// round 4
// speedup vs baseline: 2.1621x; 1.4827x over previous
#include <cuda_runtime.h>
#include <cuda_bf16.h>
#include <math.h>
#include <stdint.h>

#define Bq    4
#define Hh    12
#define Cc    1024
#define Dd    768
#define Ee    30
#define Mm    8
#define Pp    600
#define NL    97
#define RELSn 96
#define EMBn  768
#define NTOT  2400   // B*P
#define NPAD  2560   // 20 tiles of 128 (rows >= NTOT stay zero)
#define NSPLIT 12    // k blocks

// ---------------- scratch (static device globals; no allocation) -------------
__device__ float g_ent_emb[Bq*Ee*Dd];          // [B,E,D]
__device__ float g_ent_att[Bq*Ee*Hh*Cc];       // [B,E,H,C]
__device__ float g_rs[NTOT*Dd];                // [N,D] fp32
__device__ float g_hz[NPAD*EMBn];              // rows >=2400 stay zero
__device__ float g_tz[NPAD*EMBn];
__device__ uint32_t g_wt_hi[768*4096];         // bil W blobs: [blob][64 j][64 lpair]
__device__ uint32_t g_wt_lo[768*4096];
__device__ uint32_t g_ht_hi[Bq*640*512];       // ht_att bf16 pairs [b][640][512]
__device__ uint32_t g_ht_lo[Bq*640*512];
__device__ uint32_t g_seq_hi[Bq*Cc*384];       // seq bf16 pairs [b][1024][384]
__device__ uint32_t g_seq_lo[Bq*Cc*384];
__device__ uint32_t g_rs_hi[2432*384];         // rs bf16 pairs (pad rows zero)
__device__ uint32_t g_rs_lo[2432*384];
__device__ uint32_t g_wb_hi[768*768];          // [W_bot_head | W_bot_tail] pairs
__device__ uint32_t g_wb_lo[768*768];
__device__ float g_U[2*Bq*Ee*EMBn];            // ent_emb @ W_top (head, tail)
__device__ float g_RW[NTOT*1536];              // rs @ [Wbh | Wbt]
__device__ float g_part[NSPLIT*NPAD*128];      // split partial logits
__device__ float g_riskc[RELSn];

// =================== helpers ===================================================
__device__ __forceinline__ uint32_t smem_u32(const void* p) {
    uint32_t a;
    asm("{ .reg .u64 t; cvta.to.shared.u64 t, %1; cvt.u32.u64 %0, t; }" : "=r"(a) : "l"(p));
    return a;
}
__device__ __forceinline__ void pack2(float p0, float p1, uint32_t& hi, uint32_t& lo) {
    uint32_t h;
    asm("cvt.rn.bf16x2.f32 %0, %1, %2;" : "=r"(h) : "f"(p1), "f"(p0));
    float h0 = __uint_as_float(h << 16);
    float h1 = __uint_as_float(h & 0xFFFF0000u);
    float l0 = p0 - h0, l1 = p1 - h1;
    uint32_t l;
    asm("cvt.rn.bf16x2.f32 %0, %1, %2;" : "=r"(l) : "f"(l1), "f"(l0));
    hi = h; lo = l;
}
__device__ __forceinline__ void ldm_x4(uint32_t* r, uint32_t addr) {
    asm volatile("ldmatrix.sync.aligned.m8n8.x4.shared.b16 {%0,%1,%2,%3}, [%4];"
        : "=r"(r[0]), "=r"(r[1]), "=r"(r[2]), "=r"(r[3]) : "r"(addr));
}
__device__ __forceinline__ void ldm_x4_t(uint32_t* r, uint32_t addr) {
    asm volatile("ldmatrix.sync.aligned.m8n8.x4.trans.shared.b16 {%0,%1,%2,%3}, [%4];"
        : "=r"(r[0]), "=r"(r[1]), "=r"(r[2]), "=r"(r[3]) : "r"(addr));
}
__device__ __forceinline__ void mma_bf16(float* d, const uint32_t* a, const uint32_t* b) {
    asm volatile(
        "mma.sync.aligned.m16n8k16.row.col.f32.bf16.bf16.f32 "
        "{%0,%1,%2,%3}, {%4,%5,%6,%7}, {%8,%9}, {%0,%1,%2,%3};"
        : "+f"(d[0]), "+f"(d[1]), "+f"(d[2]), "+f"(d[3])
        : "r"(a[0]), "r"(a[1]), "r"(a[2]), "r"(a[3]), "r"(b[0]), "r"(b[1]));
}

// ---------------- K1: entity embeddings via weighted logsumexp ---------------
__global__ void k_ent_emb(const float* __restrict__ seq,
                          const int* __restrict__ midx,
                          const float* __restrict__ mmask) {
    int be = blockIdx.x;
    int b  = be / Ee;
    __shared__ int   s_idx[Mm];
    __shared__ float s_w[Mm];
    if (threadIdx.x < Mm) {
        s_idx[threadIdx.x] = midx[be*Mm + threadIdx.x] + 1;
        s_w[threadIdx.x]   = mmask[be*Mm + threadIdx.x];
    }
    __syncthreads();
    for (int d = threadIdx.x; d < Dd; d += blockDim.x) {
        float xv[Mm];
        float mx = -1e30f;
#pragma unroll
        for (int m = 0; m < Mm; m++) {
            float x = seq[((size_t)b*Cc + s_idx[m])*Dd + d];
            xv[m] = x;
            if (s_w[m] > 0.f) mx = fmaxf(mx, x);
        }
        float s = 0.f;
#pragma unroll
        for (int m = 0; m < Mm; m++)
            if (s_w[m] > 0.f) s += s_w[m] * __expf(xv[m] - mx);
        g_ent_emb[(size_t)be*Dd + d] = __logf(s) + mx;
    }
}

// ---------------- K2: entity attention (mask-weighted mean of rows) ----------
__global__ void k_ent_att(const float* __restrict__ att,
                          const int* __restrict__ midx,
                          const float* __restrict__ mmask) {
    int g  = blockIdx.x;
    int h  = g % Hh;
    int be = g / Hh;
    int b  = be / Ee;
    __shared__ int   s_idx[Mm];
    __shared__ float s_w[Mm];
    if (threadIdx.x < Mm) {
        s_idx[threadIdx.x] = midx[be*Mm + threadIdx.x] + 1;
        s_w[threadIdx.x]   = mmask[be*Mm + threadIdx.x];
    }
    __syncthreads();
    float cnt = 0.f;
#pragma unroll
    for (int m = 0; m < Mm; m++) cnt += s_w[m];
    float inv = 1.f / cnt;
    const float* base = att + ((size_t)b*Hh + h)*Cc*Cc;
    for (int c = threadIdx.x; c < Cc; c += blockDim.x) {
        float s = 0.f;
#pragma unroll
        for (int m = 0; m < Mm; m++)
            s += s_w[m] * base[(size_t)s_idx[m]*Cc + c];
        g_ent_att[(size_t)g*Cc + c] = s * inv;
    }
}

// ---------------- K3: ht_att -> bf16 hi/lo split --------------------------------
__global__ void k_ht(const int* __restrict__ hts) {
    int n = blockIdx.x;
    int b = n / Pp, p = n % Pp;
    int hi = hts[n*2 + 0], ti = hts[n*2 + 1];
    size_t hb = (size_t)(b*Ee + hi) * Hh * Cc;
    size_t tb = (size_t)(b*Ee + ti) * Hh * Cc;
    __shared__ float vals[Cc];
    __shared__ float red[256];
    float loc = 0.f;
    for (int c = threadIdx.x; c < Cc; c += 256) {
        float s = 0.f;
#pragma unroll
        for (int h = 0; h < Hh; h++)
            s += g_ent_att[hb + (size_t)h*Cc + c] * g_ent_att[tb + (size_t)h*Cc + c];
        s *= (1.f / Hh);
        vals[c] = s;
        loc += s;
    }
    red[threadIdx.x] = loc;
    __syncthreads();
    for (int st = 128; st > 0; st >>= 1) {
        if (threadIdx.x < st) red[threadIdx.x] += red[threadIdx.x + st];
        __syncthreads();
    }
    float invt = 1.f / (red[0] + 1e-5f);
    uint32_t* oh = g_ht_hi + ((size_t)b*640 + p)*512;
    uint32_t* ol = g_ht_lo + ((size_t)b*640 + p)*512;
    for (int c2 = threadIdx.x; c2 < 512; c2 += 256) {
        float v0 = vals[c2*2]   * invt;
        float v1 = vals[c2*2+1] * invt;
        uint32_t h, l;
        pack2(v0, v1, h, l);
        oh[c2] = h; ol[c2] = l;
    }
}

// ---------------- split kernels -------------------------------------------------
__global__ void k_seqsplit(const float* __restrict__ seq) {
    int i = blockIdx.x*256 + threadIdx.x;      // 4*1024*384
    if (i >= Bq*Cc*384) return;
    uint32_t h, l;
    pack2(seq[(size_t)i*2], seq[(size_t)i*2+1], h, l);
    g_seq_hi[i] = h; g_seq_lo[i] = l;
}
__global__ void k_rssplit() {
    int i = blockIdx.x*256 + threadIdx.x;      // 2400*384
    if (i >= NTOT*384) return;
    uint32_t h, l;
    pack2(g_rs[(size_t)i*2], g_rs[(size_t)i*2+1], h, l);
    g_rs_hi[i] = h; g_rs_lo[i] = l;
}
// W_bot concat split: [768 k][768 pairs] ; pair col c -> bf16 cols 2c,2c+1
__global__ void k_wbsplit(const float* __restrict__ hW, const float* __restrict__ tW) {
    int i = blockIdx.x*256 + threadIdx.x;      // 768*768
    if (i >= 768*768) return;
    int kk = i / 768, c = i % 768;
    int c2 = c*2;
    const float* W = (c2 < 768) ? hW : tW;
    int col = (c2 < 768) ? c2 : (c2 - 768);
    size_t ro = (size_t)(768 + kk) * EMBn;
    uint32_t h, l;
    pack2(W[ro + col], W[ro + col + 1], h, l);
    g_wb_hi[i] = h; g_wb_lo[i] = l;
}
// bil_W split: per blob(k,i): [64 j][64 lpair] (l>=97 zero)
__global__ void k_wsplit(const float* __restrict__ W) {
    int blob = blockIdx.x;
    int t = threadIdx.x;
    int j = t >> 2, lq = (t & 3) * 32;
    size_t row = ((size_t)blob*64 + j) * NL;
    uint32_t* oh = g_wt_hi + ((size_t)blob*64 + j)*64 + lq/2;
    uint32_t* ol = g_wt_lo + ((size_t)blob*64 + j)*64 + lq/2;
#pragma unroll
    for (int q = 0; q < 16; q++) {
        int l0 = lq + q*2, l1 = l0 + 1;
        float v0 = (l0 < NL) ? W[row + l0] : 0.f;
        float v1 = (l1 < NL) ? W[row + l1] : 0.f;
        uint32_t h, l;
        pack2(v0, v1, h, l);
        oh[q] = h; ol[q] = l;
    }
}

// ---------------- generic bf16x3 mma GEMM body ---------------------------------
// C[M,N] += A[M,K] * B[K,N]; A/B pre-split bf16 hi/lo, pair-packed u32, row-major.
// CTA tile 128x128, k-chunk 64, 256 thr, 8 warps (2m x 4n).
#define GA_H 0
#define GA_L 18432
#define GB_H 36864
#define GB_L 54272
#define GEMM_SM 71680

__device__ __forceinline__ void gemm_body(
    const uint32_t* __restrict__ Ah, const uint32_t* __restrict__ Al,
    const uint32_t* __restrict__ Bh, const uint32_t* __restrict__ Bl,
    float* __restrict__ C, int M, int K, int N)
{
    extern __shared__ char sm[];
    uint32_t smb = smem_u32(sm);
    int tid = threadIdx.x, lane = tid & 31, wid = tid >> 5;
    int m0 = blockIdx.x * 128, n0 = blockIdx.y * 128;
    int lda32 = K >> 1, ldb32 = N >> 1;
    int wn = wid >> 2, wl = wid & 3, lq = lane & 15, lh = lane >> 4;
    uint32_t a_base  = smb + GA_H + (wn*64 + lq)*144 + lh*16;
    uint32_t al_base = a_base + (GA_L - GA_H);
    uint32_t b_base  = smb + GB_H + lq*272 + (wl*64 + lh*16);
    uint32_t bl_base = b_base + (GB_L - GB_H);
    float acc[4][4][4] = {};
    for (int kc = 0; kc < K; kc += 64) {
#pragma unroll
        for (int rep = 0; rep < 4; rep++) {
            int idx = tid + rep*256;
            int row = idx >> 3, c4 = idx & 7;
            size_t go = (size_t)(m0 + row)*lda32 + (kc >> 1) + c4*4;
            *(uint4*)(sm + GA_H + row*144 + c4*16) = *(const uint4*)&Ah[go];
            *(uint4*)(sm + GA_L + row*144 + c4*16) = *(const uint4*)&Al[go];
        }
#pragma unroll
        for (int rep = 0; rep < 4; rep++) {
            int idx = tid + rep*256;
            int row = idx >> 4, c4 = idx & 15;
            size_t go = (size_t)(kc + row)*ldb32 + (n0 >> 1) + c4*4;
            *(uint4*)(sm + GB_H + row*272 + c4*16) = *(const uint4*)&Bh[go];
            *(uint4*)(sm + GB_L + row*272 + c4*16) = *(const uint4*)&Bl[go];
        }
        __syncthreads();
#pragma unroll
        for (int kt = 0; kt < 4; kt++) {
            uint32_t a_hi[4][4], a_lo[4][4];
#pragma unroll
            for (int mt = 0; mt < 4; mt++) {
                ldm_x4(a_hi[mt], a_base  + mt*2304 + kt*32);
                ldm_x4(a_lo[mt], al_base + mt*2304 + kt*32);
            }
#pragma unroll
            for (int lt = 0; lt < 2; lt++) {
                uint32_t b_hi[4], b_lo[4];
                ldm_x4_t(b_hi, b_base  + kt*4352 + lt*32);
                ldm_x4_t(b_lo, bl_base + kt*4352 + lt*32);
#pragma unroll
                for (int mt = 0; mt < 4; mt++) {
#pragma unroll
                    for (int f = 0; f < 2; f++) {
                        float* d = acc[mt][lt*2 + f];
                        mma_bf16(d, a_hi[mt], &b_hi[f*2]);
                        mma_bf16(d, a_lo[mt], &b_hi[f*2]);
                        mma_bf16(d, a_hi[mt], &b_lo[f*2]);
                    }
                }
            }
        }
        __syncthreads();
    }
    int rbase = m0 + wn*64 + (lane >> 2);
    int cbase = n0 + wl*32 + (lane & 3)*2;
#pragma unroll
    for (int mt = 0; mt < 4; mt++) {
#pragma unroll
        for (int lf = 0; lf < 4; lf++) {
            int r = rbase + mt*16;
            int c = cbase + lf*8;
            float* d = acc[mt][lf];
            if (r < M)     *(float2*)&C[(size_t)r*N + c]     = make_float2(d[0], d[1]);
            if (r + 8 < M) *(float2*)&C[(size_t)(r+8)*N + c] = make_float2(d[2], d[3]);
        }
    }
}

// rs = ht_att @ seq  : per-batch, M=600(pad640), K=1024, N=768
__global__ __launch_bounds__(256, 2) void k_rs_mma() {
    int b = blockIdx.z;
    gemm_body(g_ht_hi + (size_t)b*640*512, g_ht_lo + (size_t)b*640*512,
              g_seq_hi + (size_t)b*Cc*384, g_seq_lo + (size_t)b*Cc*384,
              g_rs + (size_t)b*Pp*Dd, Pp, Cc, Dd);
}
// RW = rs @ [Wbh | Wbt] : M=2400, K=768, N=1536
__global__ __launch_bounds__(256, 2) void k_rw_mma() {
    gemm_body(g_rs_hi, g_rs_lo, g_wb_hi, g_wb_lo, g_RW, NTOT, Dd, 1536);
}

// ---------------- entity-level W_top GEMM (SIMT, tiny) -------------------------
__global__ void k_entU(const float* __restrict__ hW, const float* __restrict__ tW) {
    int s = blockIdx.z;
    const float* W = s ? tW : hW;    // rows 0..767 (W_top)
    int mb = blockIdx.x * 64, nb = blockIdx.y * 64;
    __shared__ float As[16][64];
    __shared__ float Bs[16][64];
    int tid = threadIdx.x;
    int tm = tid >> 4, tn = tid & 15;
    int lm = tid & 63, lk4 = (tid >> 6) << 2;
    float acc[4][4] = {};
    for (int kc = 0; kc < Dd; kc += 16) {
        float4 av = make_float4(0.f,0.f,0.f,0.f);
        int m = mb + lm;
        if (m < Bq*Ee) av = *(const float4*)&g_ent_emb[(size_t)m*Dd + kc + lk4];
        As[lk4+0][lm] = av.x; As[lk4+1][lm] = av.y;
        As[lk4+2][lm] = av.z; As[lk4+3][lm] = av.w;
#pragma unroll
        for (int r = 0; r < 4; r++) {
            int kk = lk4 + r;
            Bs[kk][lm] = W[(size_t)(kc+kk)*EMBn + nb + lm];
        }
        __syncthreads();
#pragma unroll
        for (int kk = 0; kk < 16; kk++) {
            float4 a4 = *(const float4*)&As[kk][tm*4];
            float4 b4 = *(const float4*)&Bs[kk][tn*4];
            acc[0][0] += a4.x*b4.x; acc[0][1] += a4.x*b4.y; acc[0][2] += a4.x*b4.z; acc[0][3] += a4.x*b4.w;
            acc[1][0] += a4.y*b4.x; acc[1][1] += a4.y*b4.y; acc[1][2] += a4.y*b4.z; acc[1][3] += a4.y*b4.w;
            acc[2][0] += a4.z*b4.x; acc[2][1] += a4.z*b4.y; acc[2][2] += a4.z*b4.z; acc[2][3] += a4.z*b4.w;
            acc[3][0] += a4.w*b4.x; acc[3][1] += a4.w*b4.y; acc[3][2] += a4.w*b4.z; acc[3][3] += a4.w*b4.w;
        }
        __syncthreads();
    }
#pragma unroll
    for (int a = 0; a < 4; a++) {
        int m = mb + tm*4 + a;
        if (m < Bq*Ee)
            *(float4*)&g_U[((size_t)s*Bq*Ee + m)*EMBn + nb + tn*4] =
                make_float4(acc[a][0], acc[a][1], acc[a][2], acc[a][3]);
    }
}

// ---------------- fuse: hz/tz = tanh(gather(U) + RW + b) -----------------------
__global__ void k_tanh(const int* __restrict__ hts, const float* __restrict__ hb,
                       const float* __restrict__ tb) {
    int n = blockIdx.x;
    int b = n / Pp;
    int hi = hts[n*2 + 0], ti = hts[n*2 + 1];
    const float* Uh = g_U + (size_t)(b*Ee + hi)*EMBn;
    const float* Ut = g_U + (size_t)(Bq*Ee + b*Ee + ti)*EMBn;
    const float* rw = g_RW + (size_t)n*1536;
    int e = threadIdx.x * 4;          // 192 threads * 4 = 768
    float4 u  = *(const float4*)&Uh[e];
    float4 r  = *(const float4*)&rw[e];
    float4 bb = *(const float4*)&hb[e];
    float4 o;
    o.x = tanhf(u.x + r.x + bb.x);
    o.y = tanhf(u.y + r.y + bb.y);
    o.z = tanhf(u.z + r.z + bb.z);
    o.w = tanhf(u.w + r.w + bb.w);
    *(float4*)&g_hz[(size_t)n*EMBn + e] = o;
    float4 u2 = *(const float4*)&Ut[e];
    float4 r2 = *(const float4*)&rw[768 + e];
    float4 b2 = *(const float4*)&tb[e];
    float4 o2;
    o2.x = tanhf(u2.x + r2.x + b2.x);
    o2.y = tanhf(u2.y + r2.y + b2.y);
    o2.z = tanhf(u2.z + r2.z + b2.z);
    o2.w = tanhf(u2.w + r2.w + b2.w);
    *(float4*)&g_tz[(size_t)n*EMBn + e] = o2;
}

// ---------------- bilinear: mma.sync bf16x3, one CTA per (ntile, k) ------------
#define SM_TZ 0
#define SM_AH 32768
#define SM_AL 51200
#define SM_BH 69632
#define SM_BL 87040
#define SM_TOT 104448

__global__ __launch_bounds__(256, 2) void k_bilin_mma() {
    extern __shared__ char sm[];
    float* TZ = (float*)(sm + SM_TZ);
    uint32_t smb = smem_u32(sm);
    int tid = threadIdx.x, lane = tid & 31, wid = tid >> 5;
    int n0 = blockIdx.x * 128, k = blockIdx.y;

    for (int idx = tid; idx < 2048; idx += 256) {
        int r = idx >> 4, c = (idx & 15) * 4;
        *(float4*)&TZ[r*64 + c] = *(const float4*)&g_tz[(size_t)(n0 + r)*EMBn + k*64 + c];
    }
    int anl = tid >> 1, ajh = tid & 1;
    const float* hzp = g_hz + (size_t)(n0 + anl)*EMBn + k*64;
    int wn = wid >> 2, wl = wid & 3;
    int lq = lane & 15, lh = lane >> 4;
    uint32_t a_base  = smb + SM_AH + (wn*64 + lq)*144 + lh*16;
    uint32_t al_base = a_base + (SM_AL - SM_AH);
    uint32_t b_base  = smb + SM_BH + lq*272 + (wl*64 + lh*16);
    uint32_t bl_base = b_base + (SM_BL - SM_BH);

    float acc[4][4][4] = {};
    __syncthreads();

    for (int i = 0; i < 64; i++) {
        size_t blob4 = ((size_t)(k*64 + i)) * 1024;
        const uint4* wh  = reinterpret_cast<const uint4*>(g_wt_hi);
        const uint4* wlo = reinterpret_cast<const uint4*>(g_wt_lo);
#pragma unroll
        for (int rep = 0; rep < 4; rep++) {
            int idx = tid + rep*256;
            int j = idx >> 4, c = idx & 15;
            *(uint4*)(sm + SM_BH + j*272 + c*16) = wh[blob4 + idx];
            *(uint4*)(sm + SM_BL + j*272 + c*16) = wlo[blob4 + idx];
        }
        float hzv = hzp[i];
        const float* tzr = &TZ[anl*64 + ajh*32];
        char* ah = sm + SM_AH + anl*144 + ajh*64;
        char* al = sm + SM_AL + anl*144 + ajh*64;
#pragma unroll
        for (int g = 0; g < 4; g++) {
            float4 t0 = *(const float4*)&tzr[g*8];
            float4 t1 = *(const float4*)&tzr[g*8 + 4];
            uint32_t h[4], l[4];
            pack2(hzv*t0.x, hzv*t0.y, h[0], l[0]);
            pack2(hzv*t0.z, hzv*t0.w, h[1], l[1]);
            pack2(hzv*t1.x, hzv*t1.y, h[2], l[2]);
            pack2(hzv*t1.z, hzv*t1.w, h[3], l[3]);
            *(uint4*)(ah + g*16) = make_uint4(h[0], h[1], h[2], h[3]);
            *(uint4*)(al + g*16) = make_uint4(l[0], l[1], l[2], l[3]);
        }
        __syncthreads();
#pragma unroll
        for (int kt = 0; kt < 4; kt++) {
            uint32_t a_hi[4][4], a_lo[4][4];
#pragma unroll
            for (int mt = 0; mt < 4; mt++) {
                ldm_x4(a_hi[mt], a_base  + mt*2304 + kt*32);
                ldm_x4(a_lo[mt], al_base + mt*2304 + kt*32);
            }
#pragma unroll
            for (int lt = 0; lt < 2; lt++) {
                uint32_t b_hi[4], b_lo[4];
                ldm_x4_t(b_hi, b_base  + kt*4352 + lt*32);
                ldm_x4_t(b_lo, bl_base + kt*4352 + lt*32);
#pragma unroll
                for (int mt = 0; mt < 4; mt++) {
#pragma unroll
                    for (int f = 0; f < 2; f++) {
                        float* d = acc[mt][lt*2 + f];
                        mma_bf16(d, a_hi[mt], &b_hi[f*2]);
                        mma_bf16(d, a_lo[mt], &b_hi[f*2]);
                        mma_bf16(d, a_hi[mt], &b_lo[f*2]);
                    }
                }
            }
        }
        __syncthreads();
    }
    int rbase = n0 + wn*64 + (lane >> 2);
    int cbase = wl*32 + (lane & 3)*2;
#pragma unroll
    for (int mt = 0; mt < 4; mt++) {
#pragma unroll
        for (int lf = 0; lf < 4; lf++) {
            int r = rbase + mt*16;
            int c = cbase + lf*8;
            float* d = acc[mt][lf];
            *(float2*)&g_part[((size_t)k*NPAD + r)*128 + c]     = make_float2(d[0], d[1]);
            *(float2*)&g_part[((size_t)k*NPAD + r + 8)*128 + c] = make_float2(d[2], d[3]);
        }
    }
}

// ---------------- reduce split partials + bias -> logits -----------------------
__global__ void k_logits(const float* __restrict__ bb, float* __restrict__ out) {
    int g = blockIdx.x * 256 + threadIdx.x;
    if (g >= NTOT*NL) return;
    int n = g / NL, l = g % NL;
    float s = bb[l];
#pragma unroll
    for (int sp = 0; sp < NSPLIT; sp++)
        s += g_part[((size_t)sp*NPAD + n)*128 + l];
    out[1 + (size_t)n*NL + l] = s;
}

// ---------------- per-class S-PU risk -------------------------------------------
__global__ void k_risk(const float* __restrict__ out, const int* __restrict__ labels,
                       const float* __restrict__ pl, const float* __restrict__ po) {
    int r = blockIdx.x;
    int tid = threadIdx.x;
    float s_neg = 0.f, s_pp = 0.f, s_pn = 0.f, c_pos = 0.f;
    for (int n = tid; n < NTOT; n += 256) {
        float l0 = out[1 + (size_t)n*NL];
        float sc = out[1 + (size_t)n*NL + (r+1)] - l0;
        bool pos = labels[(size_t)n*NL + (r+1)] == 1;
        float lp = 0.25f * (sc - 1.f) * (sc - 1.f);
        float ln = 0.25f * (-sc - 1.f) * (-sc - 1.f);
        if (pos) { c_pos += 1.f; s_pp += lp; s_pn += ln; }
        else     { s_neg += ln; }
    }
    __shared__ float red[4][256];
    red[0][tid] = s_neg; red[1][tid] = s_pp; red[2][tid] = s_pn; red[3][tid] = c_pos;
    __syncthreads();
    for (int st = 128; st > 0; st >>= 1) {
        if (tid < st) {
#pragma unroll
            for (int q = 0; q < 4; q++) red[q][tid] += red[q][tid + st];
        }
        __syncthreads();
    }
    if (tid == 0) {
        float cp = red[3][0], cn = (float)NTOT - cp;
        float sq_neg = (cn > 0.f) ? red[0][0] / fmaxf(cn, 1.f) : 0.f;
        float sq_pp  = (cp > 0.f) ? red[1][0] / fmaxf(cp, 1.f) : 0.f;
        float sq_pn  = (cp > 0.f) ? red[2][0] / fmaxf(cp, 1.f) : 0.f;
        float o = po[r], lq = pl[r];
        float w  = sqrtf((1.f - o) / o);
        float pu = (o - lq) / (1.f - lq);
        float risk1 = (1.f - o)/(1.f - pu)*sq_neg - (pu - pu*o)/(1.f - pu)*sq_pn;
        float risk2 = o * sq_pp * w;
        g_riskc[r] = (risk1 < 0.f) ? -risk1 : (risk1 + risk2);
    }
}

// ---------------- sum class risks -> out[0] -------------------------------------
__global__ void k_risk_sum(float* __restrict__ out) {
    __shared__ float rr[128];
    int t = threadIdx.x;
    rr[t] = (t < RELSn) ? g_riskc[t] : 0.f;
    __syncthreads();
    for (int st = 64; st > 0; st >>= 1) {
        if (t < st) rr[t] += rr[t + st];
        __syncthreads();
    }
    if (t == 0) out[0] = rr[0];
}

// ---------------- launch ---------------------------------------------------------
extern "C" void kernel_launch(void* const* d_in, const int* in_sizes, int n_in,
                              void* d_out, int out_size) {
    const float* seq      = (const float*)d_in[0];
    const float* att      = (const float*)d_in[1];
    const int*   midx     = (const int*)  d_in[2];
    const float* mmask    = (const float*)d_in[3];
    const int*   hts      = (const int*)  d_in[4];
    const int*   labels   = (const int*)  d_in[5];
    const float* priors_l = (const float*)d_in[6];
    const float* priors_o = (const float*)d_in[7];
    const float* head_W   = (const float*)d_in[8];
    const float* head_b   = (const float*)d_in[9];
    const float* tail_W   = (const float*)d_in[10];
    const float* tail_b   = (const float*)d_in[11];
    const float* bil_W    = (const float*)d_in[12];
    const float* bil_b    = (const float*)d_in[13];
    float* out = (float*)d_out;

    cudaFuncSetAttribute(k_bilin_mma, cudaFuncAttributeMaxDynamicSharedMemorySize, SM_TOT);
    cudaFuncSetAttribute(k_rs_mma,  cudaFuncAttributeMaxDynamicSharedMemorySize, GEMM_SM);
    cudaFuncSetAttribute(k_rw_mma,  cudaFuncAttributeMaxDynamicSharedMemorySize, GEMM_SM);

    k_wsplit<<<768, 256>>>(bil_W);
    k_wbsplit<<<(768*768 + 255)/256, 256>>>(head_W, tail_W);
    k_seqsplit<<<(Bq*Cc*384 + 255)/256, 256>>>(seq);
    k_ent_emb<<<Bq*Ee, 256>>>(seq, midx, mmask);
    k_ent_att<<<Bq*Ee*Hh, 256>>>(att, midx, mmask);
    k_ht<<<NTOT, 256>>>(hts);
    k_rs_mma<<<dim3(5, 6, 4), 256, GEMM_SM>>>();
    k_rssplit<<<(NTOT*384 + 255)/256, 256>>>();
    k_entU<<<dim3(2, 12, 2), 256>>>(head_W, tail_W);
    k_rw_mma<<<dim3(19, 12, 1), 256, GEMM_SM>>>();
    k_tanh<<<NTOT, 192>>>(hts, head_b, tail_b);
    k_bilin_mma<<<dim3(20, 12), 256, SM_TOT>>>();
    k_logits<<<(NTOT*NL + 255)/256, 256>>>(bil_b, out);
    k_risk<<<RELSn, 256>>>(out, labels, priors_l, priors_o);
    k_risk_sum<<<1, 128>>>(out);
}

// round 6
// speedup vs baseline: 2.2210x; 1.0273x over previous
#include <cuda_runtime.h>
#include <cuda_bf16.h>
#include <cuda_fp16.h>
#include <math.h>
#include <stdint.h>

#define Bq    4
#define Hh    12
#define Cc    1024
#define Dd    768
#define Ee    30
#define Mm    8
#define Pp    600
#define NL    97
#define RELSn 96
#define EMBn  768
#define NTOT  2400   // B*P
#define NPAD  2560   // 10 tiles of 256 (rows >= NTOT stay zero)
#define NSPLIT 12    // k blocks

// ---------------- scratch (static device globals; no allocation) -------------
__device__ float g_ent_emb[Bq*Ee*Dd];          // [B,E,D]
__device__ float g_ent_att[Bq*Ee*Hh*Cc];       // [B,E,H,C]
__device__ float g_rs[NTOT*Dd];                // [N,D] fp32
__device__ float g_hz[NPAD*EMBn];              // rows >=2400 stay zero
__device__ float g_tz[NPAD*EMBn];
__device__ uint32_t g_wtf[768*4096];           // bil W fp16 hi: [blob][64 j][64 lpair]
__device__ uint32_t g_wtl[768*4096];           // bil W fp16 lo (residual)
__device__ uint32_t g_ht_hi[Bq*640*512];       // ht_att bf16 pairs [b][640][512]
__device__ uint32_t g_ht_lo[Bq*640*512];
__device__ uint32_t g_seq_hi[Bq*Cc*384];       // seq bf16 pairs [b][1024][384]
__device__ uint32_t g_seq_lo[Bq*Cc*384];
__device__ uint32_t g_rs_hi[2432*384];         // rs bf16 pairs (pad rows zero)
__device__ uint32_t g_rs_lo[2432*384];
__device__ uint32_t g_wb_hi[768*768];          // [W_bot_head | W_bot_tail] pairs
__device__ uint32_t g_wb_lo[768*768];
__device__ float g_U[2*Bq*Ee*EMBn];            // ent_emb @ W_top (head, tail)
__device__ float g_RW[NTOT*1536];              // rs @ [Wbh | Wbt]
__device__ float g_part[NSPLIT*NPAD*128];      // split partial logits
__device__ float g_riskc[RELSn];

// =================== helpers ===================================================
__device__ __forceinline__ uint32_t smem_u32(const void* p) {
    uint32_t a;
    asm("{ .reg .u64 t; cvta.to.shared.u64 t, %1; cvt.u32.u64 %0, t; }" : "=r"(a) : "l"(p));
    return a;
}
__device__ __forceinline__ void pack2(float p0, float p1, uint32_t& hi, uint32_t& lo) {
    uint32_t h;
    asm("cvt.rn.bf16x2.f32 %0, %1, %2;" : "=r"(h) : "f"(p1), "f"(p0));
    float h0 = __uint_as_float(h << 16);
    float h1 = __uint_as_float(h & 0xFFFF0000u);
    float l0 = p0 - h0, l1 = p1 - h1;
    uint32_t l;
    asm("cvt.rn.bf16x2.f32 %0, %1, %2;" : "=r"(l) : "f"(l1), "f"(l0));
    hi = h; lo = l;
}
// fp16 split: hi = f16x2(p0,p1), lo = f16x2 of residual
__device__ __forceinline__ void pack2h(float p0, float p1, uint32_t& hi, uint32_t& lo) {
    __half2 h = __floats2half2_rn(p0, p1);
    float2 hf = __half22float2(h);
    __half2 l = __floats2half2_rn(p0 - hf.x, p1 - hf.y);
    hi = *(uint32_t*)&h;
    lo = *(uint32_t*)&l;
}
__device__ __forceinline__ void ldm_x4(uint32_t* r, uint32_t addr) {
    asm volatile("ldmatrix.sync.aligned.m8n8.x4.shared.b16 {%0,%1,%2,%3}, [%4];"
        : "=r"(r[0]), "=r"(r[1]), "=r"(r[2]), "=r"(r[3]) : "r"(addr));
}
__device__ __forceinline__ void ldm_x4_t(uint32_t* r, uint32_t addr) {
    asm volatile("ldmatrix.sync.aligned.m8n8.x4.trans.shared.b16 {%0,%1,%2,%3}, [%4];"
        : "=r"(r[0]), "=r"(r[1]), "=r"(r[2]), "=r"(r[3]) : "r"(addr));
}
__device__ __forceinline__ void mma_bf16(float* d, const uint32_t* a, const uint32_t* b) {
    asm volatile(
        "mma.sync.aligned.m16n8k16.row.col.f32.bf16.bf16.f32 "
        "{%0,%1,%2,%3}, {%4,%5,%6,%7}, {%8,%9}, {%0,%1,%2,%3};"
        : "+f"(d[0]), "+f"(d[1]), "+f"(d[2]), "+f"(d[3])
        : "r"(a[0]), "r"(a[1]), "r"(a[2]), "r"(a[3]), "r"(b[0]), "r"(b[1]));
}
__device__ __forceinline__ void mma_f16(float* d, const uint32_t* a, const uint32_t* b) {
    asm volatile(
        "mma.sync.aligned.m16n8k16.row.col.f32.f16.f16.f32 "
        "{%0,%1,%2,%3}, {%4,%5,%6,%7}, {%8,%9}, {%0,%1,%2,%3};"
        : "+f"(d[0]), "+f"(d[1]), "+f"(d[2]), "+f"(d[3])
        : "r"(a[0]), "r"(a[1]), "r"(a[2]), "r"(a[3]), "r"(b[0]), "r"(b[1]));
}
#define CPASYNC(dst, src) asm volatile("cp.async.cg.shared.global [%0], [%1], 16;" :: "r"(dst), "l"(src))
#define CPCOMMIT()        asm volatile("cp.async.commit_group;")
#define CPWAIT(n)         asm volatile("cp.async.wait_group %0;" :: "n"(n) : "memory")

// ---------------- K1: entity embeddings via weighted logsumexp ---------------
__global__ void k_ent_emb(const float* __restrict__ seq,
                          const int* __restrict__ midx,
                          const float* __restrict__ mmask) {
    int be = blockIdx.x;
    int b  = be / Ee;
    __shared__ int   s_idx[Mm];
    __shared__ float s_w[Mm];
    if (threadIdx.x < Mm) {
        s_idx[threadIdx.x] = midx[be*Mm + threadIdx.x] + 1;
        s_w[threadIdx.x]   = mmask[be*Mm + threadIdx.x];
    }
    __syncthreads();
    for (int d = threadIdx.x; d < Dd; d += blockDim.x) {
        float xv[Mm];
        float mx = -1e30f;
#pragma unroll
        for (int m = 0; m < Mm; m++) {
            float x = seq[((size_t)b*Cc + s_idx[m])*Dd + d];
            xv[m] = x;
            if (s_w[m] > 0.f) mx = fmaxf(mx, x);
        }
        float s = 0.f;
#pragma unroll
        for (int m = 0; m < Mm; m++)
            if (s_w[m] > 0.f) s += s_w[m] * __expf(xv[m] - mx);
        g_ent_emb[(size_t)be*Dd + d] = __logf(s) + mx;
    }
}

// ---------------- K2: entity attention (mask-weighted mean of rows) ----------
__global__ void k_ent_att(const float* __restrict__ att,
                          const int* __restrict__ midx,
                          const float* __restrict__ mmask) {
    int g  = blockIdx.x;
    int h  = g % Hh;
    int be = g / Hh;
    int b  = be / Ee;
    __shared__ int   s_idx[Mm];
    __shared__ float s_w[Mm];
    if (threadIdx.x < Mm) {
        s_idx[threadIdx.x] = midx[be*Mm + threadIdx.x] + 1;
        s_w[threadIdx.x]   = mmask[be*Mm + threadIdx.x];
    }
    __syncthreads();
    float cnt = 0.f;
#pragma unroll
    for (int m = 0; m < Mm; m++) cnt += s_w[m];
    float inv = 1.f / cnt;
    const float* base = att + ((size_t)b*Hh + h)*Cc*Cc;
    for (int c = threadIdx.x; c < Cc; c += blockDim.x) {
        float s = 0.f;
#pragma unroll
        for (int m = 0; m < Mm; m++)
            s += s_w[m] * base[(size_t)s_idx[m]*Cc + c];
        g_ent_att[(size_t)g*Cc + c] = s * inv;
    }
}

// ---------------- K3: ht_att -> bf16 hi/lo split --------------------------------
__global__ void k_ht(const int* __restrict__ hts) {
    int n = blockIdx.x;
    int b = n / Pp, p = n % Pp;
    int hi = hts[n*2 + 0], ti = hts[n*2 + 1];
    size_t hb = (size_t)(b*Ee + hi) * Hh * Cc;
    size_t tb = (size_t)(b*Ee + ti) * Hh * Cc;
    __shared__ float vals[Cc];
    __shared__ float red[256];
    float loc = 0.f;
    for (int c = threadIdx.x; c < Cc; c += 256) {
        float s = 0.f;
#pragma unroll
        for (int h = 0; h < Hh; h++)
            s += g_ent_att[hb + (size_t)h*Cc + c] * g_ent_att[tb + (size_t)h*Cc + c];
        s *= (1.f / Hh);
        vals[c] = s;
        loc += s;
    }
    red[threadIdx.x] = loc;
    __syncthreads();
    for (int st = 128; st > 0; st >>= 1) {
        if (threadIdx.x < st) red[threadIdx.x] += red[threadIdx.x + st];
        __syncthreads();
    }
    float invt = 1.f / (red[0] + 1e-5f);
    uint32_t* oh = g_ht_hi + ((size_t)b*640 + p)*512;
    uint32_t* ol = g_ht_lo + ((size_t)b*640 + p)*512;
    for (int c2 = threadIdx.x; c2 < 512; c2 += 256) {
        float v0 = vals[c2*2]   * invt;
        float v1 = vals[c2*2+1] * invt;
        uint32_t h, l;
        pack2(v0, v1, h, l);
        oh[c2] = h; ol[c2] = l;
    }
}

// ---------------- split kernels -------------------------------------------------
__global__ void k_seqsplit(const float* __restrict__ seq) {
    int i = blockIdx.x*256 + threadIdx.x;
    if (i >= Bq*Cc*384) return;
    uint32_t h, l;
    pack2(seq[(size_t)i*2], seq[(size_t)i*2+1], h, l);
    g_seq_hi[i] = h; g_seq_lo[i] = l;
}
__global__ void k_rssplit() {
    int i = blockIdx.x*256 + threadIdx.x;
    if (i >= NTOT*384) return;
    uint32_t h, l;
    pack2(g_rs[(size_t)i*2], g_rs[(size_t)i*2+1], h, l);
    g_rs_hi[i] = h; g_rs_lo[i] = l;
}
__global__ void k_wbsplit(const float* __restrict__ hW, const float* __restrict__ tW) {
    int i = blockIdx.x*256 + threadIdx.x;
    if (i >= 768*768) return;
    int kk = i / 768, c = i % 768;
    int c2 = c*2;
    const float* W = (c2 < 768) ? hW : tW;
    int col = (c2 < 768) ? c2 : (c2 - 768);
    size_t ro = (size_t)(768 + kk) * EMBn;
    uint32_t h, l;
    pack2(W[ro + col], W[ro + col + 1], h, l);
    g_wb_hi[i] = h; g_wb_lo[i] = l;
}
// bil_W -> fp16 hi/lo: per blob(k,i): [64 j][64 lpair] (l>=97 zero)
__global__ void k_wsplit(const float* __restrict__ W) {
    int blob = blockIdx.x;
    int t = threadIdx.x;
    int j = t >> 2, lq = (t & 3) * 32;
    size_t row = ((size_t)blob*64 + j) * NL;
    uint32_t* oh = g_wtf + ((size_t)blob*64 + j)*64 + lq/2;
    uint32_t* ol = g_wtl + ((size_t)blob*64 + j)*64 + lq/2;
#pragma unroll
    for (int q = 0; q < 16; q++) {
        int l0 = lq + q*2, l1 = l0 + 1;
        float v0 = (l0 < NL) ? W[row + l0] : 0.f;
        float v1 = (l1 < NL) ? W[row + l1] : 0.f;
        uint32_t h, l;
        pack2h(v0, v1, h, l);
        oh[q] = h; ol[q] = l;
    }
}

// ---------------- generic bf16x3 mma GEMM body ---------------------------------
#define GA_H 0
#define GA_L 18432
#define GB_H 36864
#define GB_L 54272
#define GEMM_SM 71680

__device__ __forceinline__ void gemm_body(
    const uint32_t* __restrict__ Ah, const uint32_t* __restrict__ Al,
    const uint32_t* __restrict__ Bh, const uint32_t* __restrict__ Bl,
    float* __restrict__ C, int M, int K, int N)
{
    extern __shared__ char sm[];
    uint32_t smb = smem_u32(sm);
    int tid = threadIdx.x, lane = tid & 31, wid = tid >> 5;
    int m0 = blockIdx.x * 128, n0 = blockIdx.y * 128;
    int lda32 = K >> 1, ldb32 = N >> 1;
    int wn = wid >> 2, wl = wid & 3, lq = lane & 15, lh = lane >> 4;
    uint32_t a_base  = smb + GA_H + (wn*64 + lq)*144 + lh*16;
    uint32_t al_base = a_base + (GA_L - GA_H);
    uint32_t b_base  = smb + GB_H + lq*272 + (wl*64 + lh*16);
    uint32_t bl_base = b_base + (GB_L - GB_H);
    float acc[4][4][4] = {};
    for (int kc = 0; kc < K; kc += 64) {
#pragma unroll
        for (int rep = 0; rep < 4; rep++) {
            int idx = tid + rep*256;
            int row = idx >> 3, c4 = idx & 7;
            size_t go = (size_t)(m0 + row)*lda32 + (kc >> 1) + c4*4;
            *(uint4*)(sm + GA_H + row*144 + c4*16) = *(const uint4*)&Ah[go];
            *(uint4*)(sm + GA_L + row*144 + c4*16) = *(const uint4*)&Al[go];
        }
#pragma unroll
        for (int rep = 0; rep < 4; rep++) {
            int idx = tid + rep*256;
            int row = idx >> 4, c4 = idx & 15;
            size_t go = (size_t)(kc + row)*ldb32 + (n0 >> 1) + c4*4;
            *(uint4*)(sm + GB_H + row*272 + c4*16) = *(const uint4*)&Bh[go];
            *(uint4*)(sm + GB_L + row*272 + c4*16) = *(const uint4*)&Bl[go];
        }
        __syncthreads();
#pragma unroll
        for (int kt = 0; kt < 4; kt++) {
            uint32_t a_hi[4][4], a_lo[4][4];
#pragma unroll
            for (int mt = 0; mt < 4; mt++) {
                ldm_x4(a_hi[mt], a_base  + mt*2304 + kt*32);
                ldm_x4(a_lo[mt], al_base + mt*2304 + kt*32);
            }
#pragma unroll
            for (int lt = 0; lt < 2; lt++) {
                uint32_t b_hi[4], b_lo[4];
                ldm_x4_t(b_hi, b_base  + kt*4352 + lt*32);
                ldm_x4_t(b_lo, bl_base + kt*4352 + lt*32);
#pragma unroll
                for (int mt = 0; mt < 4; mt++) {
#pragma unroll
                    for (int f = 0; f < 2; f++) {
                        float* d = acc[mt][lt*2 + f];
                        mma_bf16(d, a_hi[mt], &b_hi[f*2]);
                        mma_bf16(d, a_lo[mt], &b_hi[f*2]);
                        mma_bf16(d, a_hi[mt], &b_lo[f*2]);
                    }
                }
            }
        }
        __syncthreads();
    }
    int rbase = m0 + wn*64 + (lane >> 2);
    int cbase = n0 + wl*32 + (lane & 3)*2;
#pragma unroll
    for (int mt = 0; mt < 4; mt++) {
#pragma unroll
        for (int lf = 0; lf < 4; lf++) {
            int r = rbase + mt*16;
            int c = cbase + lf*8;
            float* d = acc[mt][lf];
            if (r < M)     *(float2*)&C[(size_t)r*N + c]     = make_float2(d[0], d[1]);
            if (r + 8 < M) *(float2*)&C[(size_t)(r+8)*N + c] = make_float2(d[2], d[3]);
        }
    }
}

__global__ __launch_bounds__(256, 2) void k_rs_mma() {
    int b = blockIdx.z;
    gemm_body(g_ht_hi + (size_t)b*640*512, g_ht_lo + (size_t)b*640*512,
              g_seq_hi + (size_t)b*Cc*384, g_seq_lo + (size_t)b*Cc*384,
              g_rs + (size_t)b*Pp*Dd, Pp, Cc, Dd);
}
__global__ __launch_bounds__(256, 2) void k_rw_mma() {
    gemm_body(g_rs_hi, g_rs_lo, g_wb_hi, g_wb_lo, g_RW, NTOT, Dd, 1536);
}

// ---------------- entity-level W_top GEMM (SIMT, tiny) -------------------------
__global__ void k_entU(const float* __restrict__ hW, const float* __restrict__ tW) {
    int s = blockIdx.z;
    const float* W = s ? tW : hW;
    int mb = blockIdx.x * 64, nb = blockIdx.y * 64;
    __shared__ float As[16][64];
    __shared__ float Bs[16][64];
    int tid = threadIdx.x;
    int tm = tid >> 4, tn = tid & 15;
    int lm = tid & 63, lk4 = (tid >> 6) << 2;
    float acc[4][4] = {};
    for (int kc = 0; kc < Dd; kc += 16) {
        float4 av = make_float4(0.f,0.f,0.f,0.f);
        int m = mb + lm;
        if (m < Bq*Ee) av = *(const float4*)&g_ent_emb[(size_t)m*Dd + kc + lk4];
        As[lk4+0][lm] = av.x; As[lk4+1][lm] = av.y;
        As[lk4+2][lm] = av.z; As[lk4+3][lm] = av.w;
#pragma unroll
        for (int r = 0; r < 4; r++) {
            int kk = lk4 + r;
            Bs[kk][lm] = W[(size_t)(kc+kk)*EMBn + nb + lm];
        }
        __syncthreads();
#pragma unroll
        for (int kk = 0; kk < 16; kk++) {
            float4 a4 = *(const float4*)&As[kk][tm*4];
            float4 b4 = *(const float4*)&Bs[kk][tn*4];
            acc[0][0] += a4.x*b4.x; acc[0][1] += a4.x*b4.y; acc[0][2] += a4.x*b4.z; acc[0][3] += a4.x*b4.w;
            acc[1][0] += a4.y*b4.x; acc[1][1] += a4.y*b4.y; acc[1][2] += a4.y*b4.z; acc[1][3] += a4.y*b4.w;
            acc[2][0] += a4.z*b4.x; acc[2][1] += a4.z*b4.y; acc[2][2] += a4.z*b4.z; acc[2][3] += a4.z*b4.w;
            acc[3][0] += a4.w*b4.x; acc[3][1] += a4.w*b4.y; acc[3][2] += a4.w*b4.z; acc[3][3] += a4.w*b4.w;
        }
        __syncthreads();
    }
#pragma unroll
    for (int a = 0; a < 4; a++) {
        int m = mb + tm*4 + a;
        if (m < Bq*Ee)
            *(float4*)&g_U[((size_t)s*Bq*Ee + m)*EMBn + nb + tn*4] =
                make_float4(acc[a][0], acc[a][1], acc[a][2], acc[a][3]);
    }
}

// ---------------- fuse: hz/tz = tanh(gather(U) + RW + b) -----------------------
__global__ void k_tanh(const int* __restrict__ hts, const float* __restrict__ hb,
                       const float* __restrict__ tb) {
    int n = blockIdx.x;
    int b = n / Pp;
    int hi = hts[n*2 + 0], ti = hts[n*2 + 1];
    const float* Uh = g_U + (size_t)(b*Ee + hi)*EMBn;
    const float* Ut = g_U + (size_t)(Bq*Ee + b*Ee + ti)*EMBn;
    const float* rw = g_RW + (size_t)n*1536;
    int e = threadIdx.x * 4;
    float4 u  = *(const float4*)&Uh[e];
    float4 r  = *(const float4*)&rw[e];
    float4 bb = *(const float4*)&hb[e];
    float4 o;
    o.x = tanhf(u.x + r.x + bb.x);
    o.y = tanhf(u.y + r.y + bb.y);
    o.z = tanhf(u.z + r.z + bb.z);
    o.w = tanhf(u.w + r.w + bb.w);
    *(float4*)&g_hz[(size_t)n*EMBn + e] = o;
    float4 u2 = *(const float4*)&Ut[e];
    float4 r2 = *(const float4*)&rw[768 + e];
    float4 b2 = *(const float4*)&tb[e];
    float4 o2;
    o2.x = tanhf(u2.x + r2.x + b2.x);
    o2.y = tanhf(u2.y + r2.y + b2.y);
    o2.z = tanhf(u2.z + r2.z + b2.z);
    o2.w = tanhf(u2.w + r2.w + b2.w);
    *(float4*)&g_tz[(size_t)n*EMBn + e] = o2;
}

// ---------------- bilinear: fp16x3 mma, 256-row tile, cp.async dbuf B ----------
#define SB_TZ 0
#define SB_AH 65536
#define SB_AL 102400
#define SB_B0 139264
#define SB_BUF 34816
#define SB_TOT 208896

__global__ __launch_bounds__(512, 1) void k_bilin_mma() {
    extern __shared__ char sm[];
    float* TZ = (float*)(sm + SB_TZ);
    uint32_t smb = smem_u32(sm);
    int tid = threadIdx.x, lane = tid & 31, wid = tid >> 5;
    int n0 = blockIdx.x * 256, k = blockIdx.y;

    // cache tz tile fp32 (256 x 64)
    for (int idx = tid; idx < 4096; idx += 512) {
        int r = idx >> 4, c = (idx & 15) * 4;
        *(float4*)&TZ[r*64 + c] = *(const float4*)&g_tz[(size_t)(n0 + r)*EMBn + k*64 + c];
    }
    int anl = tid >> 1, ajh = tid & 1;
    const float* hzp = g_hz + (size_t)(n0 + anl)*EMBn + k*64;
    int wn = wid >> 2, wl = wid & 3;
    int lq = lane & 15, lh = lane >> 4;
    uint32_t a_base  = smb + SB_AH + (wn*64 + lq)*144 + lh*16;
    uint32_t al_base = a_base + (SB_AL - SB_AH);
    uint32_t b_frag  = lq*272 + (wl*64 + lh*16);

    // prefetch blob 0 (hi+lo) into buffer 0
    {
        const uint4* srch = ((const uint4*)g_wtf) + ((size_t)(k*64))*1024;
        const uint4* srcl = ((const uint4*)g_wtl) + ((size_t)(k*64))*1024;
#pragma unroll
        for (int rep = 0; rep < 2; rep++) {
            int idx = tid + rep*512;
            int j = idx >> 4, c = idx & 15;
            CPASYNC(smb + SB_B0 + j*272 + c*16, srch + idx);
            CPASYNC(smb + SB_B0 + 17408 + j*272 + c*16, srcl + idx);
        }
        CPCOMMIT();
    }

    float acc[4][4][4] = {};
    __syncthreads();   // TZ visible

    for (int i = 0; i < 64; i++) {
        // prefetch next blob into other buffer
        if (i < 63) {
            size_t blob = (size_t)(k*64 + i + 1) * 1024;
            const uint4* srch = ((const uint4*)g_wtf) + blob;
            const uint4* srcl = ((const uint4*)g_wtl) + blob;
            uint32_t dst = smb + SB_B0 + ((i + 1) & 1) * SB_BUF;
#pragma unroll
            for (int rep = 0; rep < 2; rep++) {
                int idx = tid + rep*512;
                int j = idx >> 4, c = idx & 15;
                CPASYNC(dst + j*272 + c*16, srch + idx);
                CPASYNC(dst + 17408 + j*272 + c*16, srcl + idx);
            }
            CPCOMMIT();
        }
        // generate A = hz[:,i] (x) tz, fp16 hi/lo
        float hzv = hzp[i];
        const float* tzr = &TZ[anl*64 + ajh*32];
        char* ah = sm + SB_AH + anl*144 + ajh*64;
        char* al = sm + SB_AL + anl*144 + ajh*64;
#pragma unroll
        for (int g = 0; g < 4; g++) {
            float4 t0 = *(const float4*)&tzr[g*8];
            float4 t1 = *(const float4*)&tzr[g*8 + 4];
            uint32_t h[4], l[4];
            pack2h(hzv*t0.x, hzv*t0.y, h[0], l[0]);
            pack2h(hzv*t0.z, hzv*t0.w, h[1], l[1]);
            pack2h(hzv*t1.x, hzv*t1.y, h[2], l[2]);
            pack2h(hzv*t1.z, hzv*t1.w, h[3], l[3]);
            *(uint4*)(ah + g*16) = make_uint4(h[0], h[1], h[2], h[3]);
            *(uint4*)(al + g*16) = make_uint4(l[0], l[1], l[2], l[3]);
        }
        if (i < 63) { CPWAIT(1); } else { CPWAIT(0); }
        __syncthreads();   // A written, B(i) landed
        uint32_t b_cur  = smb + SB_B0 + (i & 1) * SB_BUF + b_frag;
        uint32_t bl_cur = b_cur + 17408;
#pragma unroll
        for (int kt = 0; kt < 4; kt++) {
            uint32_t b_hi[2][4], b_lo[2][4];
#pragma unroll
            for (int lt = 0; lt < 2; lt++) {
                ldm_x4_t(b_hi[lt], b_cur  + kt*4352 + lt*32);
                ldm_x4_t(b_lo[lt], bl_cur + kt*4352 + lt*32);
            }
#pragma unroll
            for (int mt = 0; mt < 4; mt++) {
                uint32_t a_hi[4], a_lo[4];
                ldm_x4(a_hi, a_base  + mt*2304 + kt*32);
                ldm_x4(a_lo, al_base + mt*2304 + kt*32);
#pragma unroll
                for (int lt = 0; lt < 2; lt++) {
#pragma unroll
                    for (int f = 0; f < 2; f++) {
                        float* d = acc[mt][lt*2 + f];
                        mma_f16(d, a_hi, &b_hi[lt][f*2]);
                        mma_f16(d, a_lo, &b_hi[lt][f*2]);
                        mma_f16(d, a_hi, &b_lo[lt][f*2]);
                    }
                }
            }
        }
        __syncthreads();   // mma done reading A before next overwrite
    }
    int rbase = n0 + wn*64 + (lane >> 2);
    int cbase = wl*32 + (lane & 3)*2;
#pragma unroll
    for (int mt = 0; mt < 4; mt++) {
#pragma unroll
        for (int lf = 0; lf < 4; lf++) {
            int r = rbase + mt*16;
            int c = cbase + lf*8;
            float* d = acc[mt][lf];
            *(float2*)&g_part[((size_t)k*NPAD + r)*128 + c]     = make_float2(d[0], d[1]);
            *(float2*)&g_part[((size_t)k*NPAD + r + 8)*128 + c] = make_float2(d[2], d[3]);
        }
    }
}

// ---------------- reduce split partials + bias -> logits -----------------------
__global__ void k_logits(const float* __restrict__ bb, float* __restrict__ out) {
    int g = blockIdx.x * 256 + threadIdx.x;
    if (g >= NTOT*NL) return;
    int n = g / NL, l = g % NL;
    float s = bb[l];
#pragma unroll
    for (int sp = 0; sp < NSPLIT; sp++)
        s += g_part[((size_t)sp*NPAD + n)*128 + l];
    out[1 + (size_t)n*NL + l] = s;
}

// ---------------- per-class S-PU risk -------------------------------------------
__global__ void k_risk(const float* __restrict__ out, const int* __restrict__ labels,
                       const float* __restrict__ pl, const float* __restrict__ po) {
    int r = blockIdx.x;
    int tid = threadIdx.x;
    float s_neg = 0.f, s_pp = 0.f, s_pn = 0.f, c_pos = 0.f;
    for (int n = tid; n < NTOT; n += 256) {
        float l0 = out[1 + (size_t)n*NL];
        float sc = out[1 + (size_t)n*NL + (r+1)] - l0;
        bool pos = labels[(size_t)n*NL + (r+1)] == 1;
        float lp = 0.25f * (sc - 1.f) * (sc - 1.f);
        float ln = 0.25f * (-sc - 1.f) * (-sc - 1.f);
        if (pos) { c_pos += 1.f; s_pp += lp; s_pn += ln; }
        else     { s_neg += ln; }
    }
    __shared__ float red[4][256];
    red[0][tid] = s_neg; red[1][tid] = s_pp; red[2][tid] = s_pn; red[3][tid] = c_pos;
    __syncthreads();
    for (int st = 128; st > 0; st >>= 1) {
        if (tid < st) {
#pragma unroll
            for (int q = 0; q < 4; q++) red[q][tid] += red[q][tid + st];
        }
        __syncthreads();
    }
    if (tid == 0) {
        float cp = red[3][0], cn = (float)NTOT - cp;
        float sq_neg = (cn > 0.f) ? red[0][0] / fmaxf(cn, 1.f) : 0.f;
        float sq_pp  = (cp > 0.f) ? red[1][0] / fmaxf(cp, 1.f) : 0.f;
        float sq_pn  = (cp > 0.f) ? red[2][0] / fmaxf(cp, 1.f) : 0.f;
        float o = po[r], lq = pl[r];
        float w  = sqrtf((1.f - o) / o);
        float pu = (o - lq) / (1.f - lq);
        float risk1 = (1.f - o)/(1.f - pu)*sq_neg - (pu - pu*o)/(1.f - pu)*sq_pn;
        float risk2 = o * sq_pp * w;
        g_riskc[r] = (risk1 < 0.f) ? -risk1 : (risk1 + risk2);
    }
}

// ---------------- sum class risks -> out[0] -------------------------------------
__global__ void k_risk_sum(float* __restrict__ out) {
    __shared__ float rr[128];
    int t = threadIdx.x;
    rr[t] = (t < RELSn) ? g_riskc[t] : 0.f;
    __syncthreads();
    for (int st = 64; st > 0; st >>= 1) {
        if (t < st) rr[t] += rr[t + st];
        __syncthreads();
    }
    if (t == 0) out[0] = rr[0];
}

// ---------------- launch ---------------------------------------------------------
extern "C" void kernel_launch(void* const* d_in, const int* in_sizes, int n_in,
                              void* d_out, int out_size) {
    const float* seq      = (const float*)d_in[0];
    const float* att      = (const float*)d_in[1];
    const int*   midx     = (const int*)  d_in[2];
    const float* mmask    = (const float*)d_in[3];
    const int*   hts      = (const int*)  d_in[4];
    const int*   labels   = (const int*)  d_in[5];
    const float* priors_l = (const float*)d_in[6];
    const float* priors_o = (const float*)d_in[7];
    const float* head_W   = (const float*)d_in[8];
    const float* head_b   = (const float*)d_in[9];
    const float* tail_W   = (const float*)d_in[10];
    const float* tail_b   = (const float*)d_in[11];
    const float* bil_W    = (const float*)d_in[12];
    const float* bil_b    = (const float*)d_in[13];
    float* out = (float*)d_out;

    cudaFuncSetAttribute(k_bilin_mma, cudaFuncAttributeMaxDynamicSharedMemorySize, SB_TOT);
    cudaFuncSetAttribute(k_rs_mma,  cudaFuncAttributeMaxDynamicSharedMemorySize, GEMM_SM);
    cudaFuncSetAttribute(k_rw_mma,  cudaFuncAttributeMaxDynamicSharedMemorySize, GEMM_SM);

    k_wsplit<<<768, 256>>>(bil_W);
    k_wbsplit<<<(768*768 + 255)/256, 256>>>(head_W, tail_W);
    k_seqsplit<<<(Bq*Cc*384 + 255)/256, 256>>>(seq);
    k_ent_emb<<<Bq*Ee, 256>>>(seq, midx, mmask);
    k_ent_att<<<Bq*Ee*Hh, 256>>>(att, midx, mmask);
    k_ht<<<NTOT, 256>>>(hts);
    k_rs_mma<<<dim3(5, 6, 4), 256, GEMM_SM>>>();
    k_rssplit<<<(NTOT*384 + 255)/256, 256>>>();
    k_entU<<<dim3(2, 12, 2), 256>>>(head_W, tail_W);
    k_rw_mma<<<dim3(19, 12, 1), 256, GEMM_SM>>>();
    k_tanh<<<NTOT, 192>>>(hts, head_b, tail_b);
    k_bilin_mma<<<dim3(10, 12), 512, SB_TOT>>>();
    k_logits<<<(NTOT*NL + 255)/256, 256>>>(bil_b, out);
    k_risk<<<RELSn, 256>>>(out, labels, priors_l, priors_o);
    k_risk_sum<<<1, 128>>>(out);
}

// round 7
// speedup vs baseline: 2.3502x; 1.0582x over previous
#include <cuda_runtime.h>
#include <cuda_bf16.h>
#include <cuda_fp16.h>
#include <math.h>
#include <stdint.h>

#define Bq    4
#define Hh    12
#define Cc    1024
#define Dd    768
#define Ee    30
#define Mm    8
#define Pp    600
#define NL    97
#define RELSn 96
#define EMBn  768
#define NTOT  2400   // B*P
#define NPAD  2560   // 10 tiles of 256 (rows >= NTOT stay zero)
#define NSPLIT 12    // k blocks

// ---------------- scratch (static device globals; no allocation) -------------
__device__ float g_ent_emb[Bq*Ee*Dd];          // [B,E,D]
__device__ float g_ent_att[Bq*Ee*Hh*Cc];       // [B,E,H,C]
__device__ float g_hz[NPAD*EMBn];              // rows >=2400 stay zero
__device__ float g_tz[NPAD*EMBn];
__device__ uint32_t g_wtf[768*3072];           // bil W fp16 hi: [blob][64 j][48 lpair]
__device__ uint32_t g_wtl[768*3072];           // bil W fp16 lo (residual)
__device__ float    g_w96[768*64];             // bil W col 96: [blob][j]
__device__ uint32_t g_ht_hi[Bq*640*512];       // ht_att bf16 pairs [b][640][512]
__device__ uint32_t g_ht_lo[Bq*640*512];
__device__ uint32_t g_seq_hi[Bq*Cc*384];       // seq bf16 pairs [b][1024][384]
__device__ uint32_t g_seq_lo[Bq*Cc*384];
__device__ uint32_t g_rs_hi[2432*384];         // rs bf16 pairs (pad rows zero)
__device__ uint32_t g_rs_lo[2432*384];
__device__ uint32_t g_wb_hi[768*768];          // [W_bot_head | W_bot_tail] pairs
__device__ uint32_t g_wb_lo[768*768];
__device__ float g_U[2*Bq*Ee*EMBn];            // ent_emb @ W_top (head, tail)
__device__ float g_part[NSPLIT*NPAD*128];      // split partial logits
__device__ float g_riskc[RELSn];

// =================== helpers ===================================================
__device__ __forceinline__ uint32_t smem_u32(const void* p) {
    uint32_t a;
    asm("{ .reg .u64 t; cvta.to.shared.u64 t, %1; cvt.u32.u64 %0, t; }" : "=r"(a) : "l"(p));
    return a;
}
__device__ __forceinline__ void pack2(float p0, float p1, uint32_t& hi, uint32_t& lo) {
    uint32_t h;
    asm("cvt.rn.bf16x2.f32 %0, %1, %2;" : "=r"(h) : "f"(p1), "f"(p0));
    float h0 = __uint_as_float(h << 16);
    float h1 = __uint_as_float(h & 0xFFFF0000u);
    float l0 = p0 - h0, l1 = p1 - h1;
    uint32_t l;
    asm("cvt.rn.bf16x2.f32 %0, %1, %2;" : "=r"(l) : "f"(l1), "f"(l0));
    hi = h; lo = l;
}
__device__ __forceinline__ void pack2h(float p0, float p1, uint32_t& hi, uint32_t& lo) {
    __half2 h = __floats2half2_rn(p0, p1);
    float2 hf = __half22float2(h);
    __half2 l = __floats2half2_rn(p0 - hf.x, p1 - hf.y);
    hi = *(uint32_t*)&h;
    lo = *(uint32_t*)&l;
}
__device__ __forceinline__ void ldm_x4(uint32_t* r, uint32_t addr) {
    asm volatile("ldmatrix.sync.aligned.m8n8.x4.shared.b16 {%0,%1,%2,%3}, [%4];"
        : "=r"(r[0]), "=r"(r[1]), "=r"(r[2]), "=r"(r[3]) : "r"(addr));
}
__device__ __forceinline__ void ldm_x4_t(uint32_t* r, uint32_t addr) {
    asm volatile("ldmatrix.sync.aligned.m8n8.x4.trans.shared.b16 {%0,%1,%2,%3}, [%4];"
        : "=r"(r[0]), "=r"(r[1]), "=r"(r[2]), "=r"(r[3]) : "r"(addr));
}
__device__ __forceinline__ void ldm_x2_t(uint32_t* r, uint32_t addr) {
    asm volatile("ldmatrix.sync.aligned.m8n8.x2.trans.shared.b16 {%0,%1}, [%2];"
        : "=r"(r[0]), "=r"(r[1]) : "r"(addr));
}
__device__ __forceinline__ void mma_bf16(float* d, const uint32_t* a, const uint32_t* b) {
    asm volatile(
        "mma.sync.aligned.m16n8k16.row.col.f32.bf16.bf16.f32 "
        "{%0,%1,%2,%3}, {%4,%5,%6,%7}, {%8,%9}, {%0,%1,%2,%3};"
        : "+f"(d[0]), "+f"(d[1]), "+f"(d[2]), "+f"(d[3])
        : "r"(a[0]), "r"(a[1]), "r"(a[2]), "r"(a[3]), "r"(b[0]), "r"(b[1]));
}
__device__ __forceinline__ void mma_f16(float* d, const uint32_t* a, const uint32_t* b) {
    asm volatile(
        "mma.sync.aligned.m16n8k16.row.col.f32.f16.f16.f32 "
        "{%0,%1,%2,%3}, {%4,%5,%6,%7}, {%8,%9}, {%0,%1,%2,%3};"
        : "+f"(d[0]), "+f"(d[1]), "+f"(d[2]), "+f"(d[3])
        : "r"(a[0]), "r"(a[1]), "r"(a[2]), "r"(a[3]), "r"(b[0]), "r"(b[1]));
}
#define CPASYNC(dst, src) asm volatile("cp.async.cg.shared.global [%0], [%1], 16;" :: "r"(dst), "l"(src))
#define CPCOMMIT()        asm volatile("cp.async.commit_group;")
#define CPWAIT(n)         asm volatile("cp.async.wait_group %0;" :: "n"(n) : "memory")

// ---------------- K1: entity embeddings via weighted logsumexp ---------------
__global__ void k_ent_emb(const float* __restrict__ seq,
                          const int* __restrict__ midx,
                          const float* __restrict__ mmask) {
    int be = blockIdx.x;
    int b  = be / Ee;
    __shared__ int   s_idx[Mm];
    __shared__ float s_w[Mm];
    if (threadIdx.x < Mm) {
        s_idx[threadIdx.x] = midx[be*Mm + threadIdx.x] + 1;
        s_w[threadIdx.x]   = mmask[be*Mm + threadIdx.x];
    }
    __syncthreads();
    for (int d = threadIdx.x; d < Dd; d += blockDim.x) {
        float xv[Mm];
        float mx = -1e30f;
#pragma unroll
        for (int m = 0; m < Mm; m++) {
            float x = seq[((size_t)b*Cc + s_idx[m])*Dd + d];
            xv[m] = x;
            if (s_w[m] > 0.f) mx = fmaxf(mx, x);
        }
        float s = 0.f;
#pragma unroll
        for (int m = 0; m < Mm; m++)
            if (s_w[m] > 0.f) s += s_w[m] * __expf(xv[m] - mx);
        g_ent_emb[(size_t)be*Dd + d] = __logf(s) + mx;
    }
}

// ---------------- K2: entity attention (mask-weighted mean of rows) ----------
__global__ void k_ent_att(const float* __restrict__ att,
                          const int* __restrict__ midx,
                          const float* __restrict__ mmask) {
    int g  = blockIdx.x;
    int h  = g % Hh;
    int be = g / Hh;
    int b  = be / Ee;
    __shared__ int   s_idx[Mm];
    __shared__ float s_w[Mm];
    if (threadIdx.x < Mm) {
        s_idx[threadIdx.x] = midx[be*Mm + threadIdx.x] + 1;
        s_w[threadIdx.x]   = mmask[be*Mm + threadIdx.x];
    }
    __syncthreads();
    float cnt = 0.f;
#pragma unroll
    for (int m = 0; m < Mm; m++) cnt += s_w[m];
    float inv = 1.f / cnt;
    const float* base = att + ((size_t)b*Hh + h)*Cc*Cc;
    for (int c = threadIdx.x; c < Cc; c += blockDim.x) {
        float s = 0.f;
#pragma unroll
        for (int m = 0; m < Mm; m++)
            s += s_w[m] * base[(size_t)s_idx[m]*Cc + c];
        g_ent_att[(size_t)g*Cc + c] = s * inv;
    }
}

// ---------------- K3: ht_att -> bf16 hi/lo split --------------------------------
__global__ void k_ht(const int* __restrict__ hts) {
    int n = blockIdx.x;
    int b = n / Pp, p = n % Pp;
    int hi = hts[n*2 + 0], ti = hts[n*2 + 1];
    size_t hb = (size_t)(b*Ee + hi) * Hh * Cc;
    size_t tb = (size_t)(b*Ee + ti) * Hh * Cc;
    __shared__ float vals[Cc];
    __shared__ float red[256];
    float loc = 0.f;
    for (int c = threadIdx.x; c < Cc; c += 256) {
        float s = 0.f;
#pragma unroll
        for (int h = 0; h < Hh; h++)
            s += g_ent_att[hb + (size_t)h*Cc + c] * g_ent_att[tb + (size_t)h*Cc + c];
        s *= (1.f / Hh);
        vals[c] = s;
        loc += s;
    }
    red[threadIdx.x] = loc;
    __syncthreads();
    for (int st = 128; st > 0; st >>= 1) {
        if (threadIdx.x < st) red[threadIdx.x] += red[threadIdx.x + st];
        __syncthreads();
    }
    float invt = 1.f / (red[0] + 1e-5f);
    uint32_t* oh = g_ht_hi + ((size_t)b*640 + p)*512;
    uint32_t* ol = g_ht_lo + ((size_t)b*640 + p)*512;
    for (int c2 = threadIdx.x; c2 < 512; c2 += 256) {
        float v0 = vals[c2*2]   * invt;
        float v1 = vals[c2*2+1] * invt;
        uint32_t h, l;
        pack2(v0, v1, h, l);
        oh[c2] = h; ol[c2] = l;
    }
}

// ---------------- split kernels -------------------------------------------------
__global__ void k_seqsplit(const float* __restrict__ seq) {
    int i = blockIdx.x*256 + threadIdx.x;
    if (i >= Bq*Cc*384) return;
    uint32_t h, l;
    pack2(seq[(size_t)i*2], seq[(size_t)i*2+1], h, l);
    g_seq_hi[i] = h; g_seq_lo[i] = l;
}
__global__ void k_wbsplit(const float* __restrict__ hW, const float* __restrict__ tW) {
    int i = blockIdx.x*256 + threadIdx.x;
    if (i >= 768*768) return;
    int kk = i / 768, c = i % 768;
    int c2 = c*2;
    const float* W = (c2 < 768) ? hW : tW;
    int col = (c2 < 768) ? c2 : (c2 - 768);
    size_t ro = (size_t)(768 + kk) * EMBn;
    uint32_t h, l;
    pack2(W[ro + col], W[ro + col + 1], h, l);
    g_wb_hi[i] = h; g_wb_lo[i] = l;
}
// bil_W -> fp16 hi/lo for cols [0,96), plus fp32 col 96
__global__ void k_wsplit(const float* __restrict__ W) {
    int blob = blockIdx.x;
    int t = threadIdx.x;                 // 256
    int j = t >> 2, lq = (t & 3) * 24;
    size_t row = ((size_t)blob*64 + j) * NL;
    uint32_t* oh = g_wtf + ((size_t)blob*64 + j)*48 + (lq >> 1);
    uint32_t* ol = g_wtl + ((size_t)blob*64 + j)*48 + (lq >> 1);
#pragma unroll
    for (int q = 0; q < 12; q++) {
        int l0 = lq + q*2;
        float v0 = W[row + l0];
        float v1 = W[row + l0 + 1];
        uint32_t h, l;
        pack2h(v0, v1, h, l);
        oh[q] = h; ol[q] = l;
    }
    if ((t & 3) == 0) g_w96[(size_t)blob*64 + j] = W[row + 96];
}

// ---------------- bf16x3 mma GEMM mainloop (128x128 tile, 256 thr) -------------
#define GA_H 0
#define GA_L 18432
#define GB_H 36864
#define GB_L 54272
#define GEMM_SM 71680

__device__ __forceinline__ void gemm_main(float acc[4][4][4],
    const uint32_t* __restrict__ Ah, const uint32_t* __restrict__ Al,
    const uint32_t* __restrict__ Bh, const uint32_t* __restrict__ Bl,
    int K, int N, int m0, int n0)
{
    extern __shared__ char sm[];
    uint32_t smb = smem_u32(sm);
    int tid = threadIdx.x, lane = tid & 31, wid = tid >> 5;
    int lda32 = K >> 1, ldb32 = N >> 1;
    int wn = wid >> 2, wl = wid & 3, lq = lane & 15, lh = lane >> 4;
    uint32_t a_base  = smb + GA_H + (wn*64 + lq)*144 + lh*16;
    uint32_t al_base = a_base + (GA_L - GA_H);
    uint32_t b_base  = smb + GB_H + lq*272 + (wl*64 + lh*16);
    uint32_t bl_base = b_base + (GB_L - GB_H);
    for (int kc = 0; kc < K; kc += 64) {
#pragma unroll
        for (int rep = 0; rep < 4; rep++) {
            int idx = tid + rep*256;
            int row = idx >> 3, c4 = idx & 7;
            size_t go = (size_t)(m0 + row)*lda32 + (kc >> 1) + c4*4;
            *(uint4*)(sm + GA_H + row*144 + c4*16) = *(const uint4*)&Ah[go];
            *(uint4*)(sm + GA_L + row*144 + c4*16) = *(const uint4*)&Al[go];
        }
#pragma unroll
        for (int rep = 0; rep < 4; rep++) {
            int idx = tid + rep*256;
            int row = idx >> 4, c4 = idx & 15;
            size_t go = (size_t)(kc + row)*ldb32 + (n0 >> 1) + c4*4;
            *(uint4*)(sm + GB_H + row*272 + c4*16) = *(const uint4*)&Bh[go];
            *(uint4*)(sm + GB_L + row*272 + c4*16) = *(const uint4*)&Bl[go];
        }
        __syncthreads();
#pragma unroll
        for (int kt = 0; kt < 4; kt++) {
            uint32_t a_hi[4][4], a_lo[4][4];
#pragma unroll
            for (int mt = 0; mt < 4; mt++) {
                ldm_x4(a_hi[mt], a_base  + mt*2304 + kt*32);
                ldm_x4(a_lo[mt], al_base + mt*2304 + kt*32);
            }
#pragma unroll
            for (int lt = 0; lt < 2; lt++) {
                uint32_t b_hi[4], b_lo[4];
                ldm_x4_t(b_hi, b_base  + kt*4352 + lt*32);
                ldm_x4_t(b_lo, bl_base + kt*4352 + lt*32);
#pragma unroll
                for (int mt = 0; mt < 4; mt++) {
#pragma unroll
                    for (int f = 0; f < 2; f++) {
                        float* d = acc[mt][lt*2 + f];
                        mma_bf16(d, a_hi[mt], &b_hi[f*2]);
                        mma_bf16(d, a_lo[mt], &b_hi[f*2]);
                        mma_bf16(d, a_hi[mt], &b_lo[f*2]);
                    }
                }
            }
        }
        __syncthreads();
    }
}

// rs = ht_att @ seq, epilogue writes bf16 hi/lo pairs directly
__global__ __launch_bounds__(256, 2) void k_rs_mma() {
    int b = blockIdx.z;
    int m0 = blockIdx.x * 128, n0 = blockIdx.y * 128;
    float acc[4][4][4] = {};
    gemm_main(acc,
              g_ht_hi + (size_t)b*640*512, g_ht_lo + (size_t)b*640*512,
              g_seq_hi + (size_t)b*Cc*384, g_seq_lo + (size_t)b*Cc*384,
              Cc, Dd, m0, n0);
    int tid = threadIdx.x, lane = tid & 31, wid = tid >> 5;
    int wn = wid >> 2, wl = wid & 3;
    int rbase = m0 + wn*64 + (lane >> 2);
    int cbase = n0 + wl*32 + (lane & 3)*2;
#pragma unroll
    for (int mt = 0; mt < 4; mt++) {
#pragma unroll
        for (int lf = 0; lf < 4; lf++) {
            int r = rbase + mt*16;
            int cp = (cbase + lf*8) >> 1;
            float* d = acc[mt][lf];
            if (r < Pp) {
                uint32_t h, l;
                pack2(d[0], d[1], h, l);
                g_rs_hi[((size_t)(b*Pp + r))*384 + cp] = h;
                g_rs_lo[((size_t)(b*Pp + r))*384 + cp] = l;
            }
            if (r + 8 < Pp) {
                uint32_t h, l;
                pack2(d[2], d[3], h, l);
                g_rs_hi[((size_t)(b*Pp + r + 8))*384 + cp] = h;
                g_rs_lo[((size_t)(b*Pp + r + 8))*384 + cp] = l;
            }
        }
    }
}

// RW = rs @ [Wbh|Wbt]; epilogue fuses U-gather + bias + tanh -> g_hz/g_tz
__global__ __launch_bounds__(256, 2) void k_rw_mma(const int* __restrict__ hts,
                                                   const float* __restrict__ hb,
                                                   const float* __restrict__ tb) {
    int m0 = blockIdx.x * 128, n0 = blockIdx.y * 128;
    float acc[4][4][4] = {};
    gemm_main(acc, g_rs_hi, g_rs_lo, g_wb_hi, g_wb_lo, Dd, 1536, m0, n0);
    int tid = threadIdx.x, lane = tid & 31, wid = tid >> 5;
    int wn = wid >> 2, wl = wid & 3;
    int rbase = m0 + wn*64 + (lane >> 2);
    int cbase = n0 + wl*32 + (lane & 3)*2;
#pragma unroll
    for (int mt = 0; mt < 4; mt++) {
#pragma unroll
        for (int rr = 0; rr < 2; rr++) {
            int r = rbase + mt*16 + rr*8;
            if (r >= NTOT) continue;
            int b = r / Pp;
            int e0 = hts[r*2 + 0], e1 = hts[r*2 + 1];
#pragma unroll
            for (int lf = 0; lf < 4; lf++) {
                int c = cbase + lf*8;
                int s = (c >= 768);
                int cc = c - (s ? 768 : 0);
                int e = s ? e1 : e0;
                const float* Ur = g_U + ((size_t)(s*Bq*Ee + b*Ee + e))*EMBn + cc;
                const float* bi = (s ? tb : hb) + cc;
                float* dst = (s ? g_tz : g_hz) + (size_t)r*EMBn + cc;
                float* d = acc[mt][lf];
                float2 o;
                o.x = tanhf(d[rr*2 + 0] + Ur[0] + bi[0]);
                o.y = tanhf(d[rr*2 + 1] + Ur[1] + bi[1]);
                *(float2*)dst = o;
            }
        }
    }
}

// ---------------- entity-level W_top GEMM (SIMT, tiny) -------------------------
__global__ void k_entU(const float* __restrict__ hW, const float* __restrict__ tW) {
    int s = blockIdx.z;
    const float* W = s ? tW : hW;
    int mb = blockIdx.x * 64, nb = blockIdx.y * 64;
    __shared__ float As[16][64];
    __shared__ float Bs[16][64];
    int tid = threadIdx.x;
    int tm = tid >> 4, tn = tid & 15;
    int lm = tid & 63, lk4 = (tid >> 6) << 2;
    float acc[4][4] = {};
    for (int kc = 0; kc < Dd; kc += 16) {
        float4 av = make_float4(0.f,0.f,0.f,0.f);
        int m = mb + lm;
        if (m < Bq*Ee) av = *(const float4*)&g_ent_emb[(size_t)m*Dd + kc + lk4];
        As[lk4+0][lm] = av.x; As[lk4+1][lm] = av.y;
        As[lk4+2][lm] = av.z; As[lk4+3][lm] = av.w;
#pragma unroll
        for (int r = 0; r < 4; r++) {
            int kk = lk4 + r;
            Bs[kk][lm] = W[(size_t)(kc+kk)*EMBn + nb + lm];
        }
        __syncthreads();
#pragma unroll
        for (int kk = 0; kk < 16; kk++) {
            float4 a4 = *(const float4*)&As[kk][tm*4];
            float4 b4 = *(const float4*)&Bs[kk][tn*4];
            acc[0][0] += a4.x*b4.x; acc[0][1] += a4.x*b4.y; acc[0][2] += a4.x*b4.z; acc[0][3] += a4.x*b4.w;
            acc[1][0] += a4.y*b4.x; acc[1][1] += a4.y*b4.y; acc[1][2] += a4.y*b4.z; acc[1][3] += a4.y*b4.w;
            acc[2][0] += a4.z*b4.x; acc[2][1] += a4.z*b4.y; acc[2][2] += a4.z*b4.z; acc[2][3] += a4.z*b4.w;
            acc[3][0] += a4.w*b4.x; acc[3][1] += a4.w*b4.y; acc[3][2] += a4.w*b4.z; acc[3][3] += a4.w*b4.w;
        }
        __syncthreads();
    }
#pragma unroll
    for (int a = 0; a < 4; a++) {
        int m = mb + tm*4 + a;
        if (m < Bq*Ee)
            *(float4*)&g_U[((size_t)s*Bq*Ee + m)*EMBn + nb + tn*4] =
                make_float4(acc[a][0], acc[a][1], acc[a][2], acc[a][3]);
    }
}

// ---------------- bilinear: fp16x3 mma, N=96, 256-row tile, cp.async dbuf ------
#define SB_TZ 0
#define SB_AH 65536
#define SB_AL 102400
#define SB_B0 139264
#define SB_BUF 26624     // hi 13312 + lo 13312 (64 rows x 208B)
#define SB_TOT 192512

__global__ __launch_bounds__(512, 1) void k_bilin_mma() {
    extern __shared__ char sm[];
    float* TZ = (float*)(sm + SB_TZ);
    uint32_t smb = smem_u32(sm);
    int tid = threadIdx.x, lane = tid & 31, wid = tid >> 5;
    int n0 = blockIdx.x * 256, k = blockIdx.y;

    // cache tz tile fp32 (256 x 64)
    for (int idx = tid; idx < 4096; idx += 512) {
        int r = idx >> 4, c = (idx & 15) * 4;
        *(float4*)&TZ[r*64 + c] = *(const float4*)&g_tz[(size_t)(n0 + r)*EMBn + k*64 + c];
    }
    int anl = tid >> 1, ajh = tid & 1;
    const float* hzp = g_hz + (size_t)(n0 + anl)*EMBn + k*64;
    int wn = wid >> 2, wl = wid & 3;
    int lq = lane & 15, lh = lane >> 4;
    uint32_t a_base  = smb + SB_AH + (wn*64 + lq)*144 + lh*16;
    uint32_t al_base = a_base + (SB_AL - SB_AH);
    uint32_t b_off4  = lq*208 + wl*48 + lh*16;           // x4: 16 cols
    uint32_t b_off2  = (lane & 15)*208 + wl*48 + 32;     // x2: 8 cols

    // prefetch blob 0 (hi+lo) into buffer 0; 768 uint4 per half
    {
        const uint4* srch = ((const uint4*)g_wtf) + (size_t)(k*64)*768;
        const uint4* srcl = ((const uint4*)g_wtl) + (size_t)(k*64)*768;
        {
            int idx = tid;
            if (idx < 768) {
                int j = idx / 12, c = idx % 12;
                CPASYNC(smb + SB_B0 + j*208 + c*16, srch + idx);
                CPASYNC(smb + SB_B0 + 13312 + j*208 + c*16, srcl + idx);
            }
            idx = tid + 512;
            if (idx < 768) {
                int j = idx / 12, c = idx % 12;
                CPASYNC(smb + SB_B0 + j*208 + c*16, srch + idx);
                CPASYNC(smb + SB_B0 + 13312 + j*208 + c*16, srcl + idx);
            }
        }
        CPCOMMIT();
    }

    float acc[4][3][4] = {};
    __syncthreads();

    for (int i = 0; i < 64; i++) {
        if (i < 63) {
            size_t blob = (size_t)(k*64 + i + 1) * 768;
            const uint4* srch = ((const uint4*)g_wtf) + blob;
            const uint4* srcl = ((const uint4*)g_wtl) + blob;
            uint32_t dst = smb + SB_B0 + ((i + 1) & 1) * SB_BUF;
            int idx = tid;
            if (idx < 768) {
                int j = idx / 12, c = idx % 12;
                CPASYNC(dst + j*208 + c*16, srch + idx);
                CPASYNC(dst + 13312 + j*208 + c*16, srcl + idx);
            }
            idx = tid + 512;
            if (idx < 768) {
                int j = idx / 12, c = idx % 12;
                CPASYNC(dst + j*208 + c*16, srch + idx);
                CPASYNC(dst + 13312 + j*208 + c*16, srcl + idx);
            }
            CPCOMMIT();
        }
        // generate A = hz[:,i] (x) tz, fp16 hi/lo
        float hzv = hzp[i];
        const float* tzr = &TZ[anl*64 + ajh*32];
        char* ah = sm + SB_AH + anl*144 + ajh*64;
        char* al = sm + SB_AL + anl*144 + ajh*64;
#pragma unroll
        for (int g = 0; g < 4; g++) {
            float4 t0 = *(const float4*)&tzr[g*8];
            float4 t1 = *(const float4*)&tzr[g*8 + 4];
            uint32_t h[4], l[4];
            pack2h(hzv*t0.x, hzv*t0.y, h[0], l[0]);
            pack2h(hzv*t0.z, hzv*t0.w, h[1], l[1]);
            pack2h(hzv*t1.x, hzv*t1.y, h[2], l[2]);
            pack2h(hzv*t1.z, hzv*t1.w, h[3], l[3]);
            *(uint4*)(ah + g*16) = make_uint4(h[0], h[1], h[2], h[3]);
            *(uint4*)(al + g*16) = make_uint4(l[0], l[1], l[2], l[3]);
        }
        if (i < 63) { CPWAIT(1); } else { CPWAIT(0); }
        __syncthreads();
        uint32_t bhi = smb + SB_B0 + (i & 1) * SB_BUF;
        uint32_t blo = bhi + 13312;
#pragma unroll
        for (int kt = 0; kt < 4; kt++) {
            uint32_t bh4[4], bl4[4], bh2[2], bl2[2];
            ldm_x4_t(bh4, bhi + b_off4 + kt*3328);
            ldm_x2_t(bh2, bhi + b_off2 + kt*3328);
            ldm_x4_t(bl4, blo + b_off4 + kt*3328);
            ldm_x2_t(bl2, blo + b_off2 + kt*3328);
#pragma unroll
            for (int mt = 0; mt < 4; mt++) {
                uint32_t a_hi[4], a_lo[4];
                ldm_x4(a_hi, a_base  + mt*2304 + kt*32);
                ldm_x4(a_lo, al_base + mt*2304 + kt*32);
#pragma unroll
                for (int nf = 0; nf < 2; nf++) {
                    float* d = acc[mt][nf];
                    mma_f16(d, a_hi, &bh4[nf*2]);
                    mma_f16(d, a_lo, &bh4[nf*2]);
                    mma_f16(d, a_hi, &bl4[nf*2]);
                }
                float* d2 = acc[mt][2];
                mma_f16(d2, a_hi, bh2);
                mma_f16(d2, a_lo, bh2);
                mma_f16(d2, a_hi, bl2);
            }
        }
        __syncthreads();
    }
    int rbase = n0 + wn*64 + (lane >> 2);
    int cbase = wl*24 + (lane & 3)*2;
#pragma unroll
    for (int mt = 0; mt < 4; mt++) {
#pragma unroll
        for (int lf = 0; lf < 3; lf++) {
            int r = rbase + mt*16;
            int c = cbase + lf*8;
            float* d = acc[mt][lf];
            *(float2*)&g_part[((size_t)k*NPAD + r)*128 + c]     = make_float2(d[0], d[1]);
            *(float2*)&g_part[((size_t)k*NPAD + r + 8)*128 + c] = make_float2(d[2], d[3]);
        }
    }
}

// ---------------- column 96 of the bilinear (exact fp32 SIMT) -------------------
#define C96_SM 82944   // W 16384 + hz 33280 + tz 33280

__global__ __launch_bounds__(128) void k_c96() {
    extern __shared__ float cs[];
    float* Ws  = cs;             // [64][64]
    float* hzs = cs + 4096;      // [128][65]
    float* tzs = hzs + 128*65;   // [128][65]
    int tid = threadIdx.x;
    int n0 = blockIdx.x * 128, k = blockIdx.y;
    for (int idx = tid; idx < 4096; idx += 128)
        Ws[idx] = g_w96[(size_t)k*4096 + idx];
    for (int idx = tid; idx < 128*64; idx += 128) {
        int r = idx >> 6, c = idx & 63;
        int n = n0 + r;
        float hv = 0.f, tv = 0.f;
        if (n < NTOT) {
            hv = g_hz[(size_t)n*EMBn + k*64 + c];
            tv = g_tz[(size_t)n*EMBn + k*64 + c];
        }
        hzs[r*65 + c] = hv;
        tzs[r*65 + c] = tv;
    }
    __syncthreads();
    float tzr[64];
#pragma unroll
    for (int j = 0; j < 64; j++) tzr[j] = tzs[tid*65 + j];
    float acc = 0.f;
    for (int i = 0; i < 64; i++) {
        const float4* wr = (const float4*)&Ws[i*64];
        float s = 0.f;
#pragma unroll
        for (int j4 = 0; j4 < 16; j4++) {
            float4 w = wr[j4];
            s += w.x*tzr[j4*4] + w.y*tzr[j4*4+1] + w.z*tzr[j4*4+2] + w.w*tzr[j4*4+3];
        }
        acc += hzs[tid*65 + i] * s;
    }
    int n = n0 + tid;
    if (n < NTOT) g_part[((size_t)k*NPAD + n)*128 + 96] = acc;
}

// ---------------- reduce split partials + bias -> logits -----------------------
__global__ void k_logits(const float* __restrict__ bb, float* __restrict__ out) {
    int g = blockIdx.x * 256 + threadIdx.x;
    if (g >= NTOT*NL) return;
    int n = g / NL, l = g % NL;
    float s = bb[l];
#pragma unroll
    for (int sp = 0; sp < NSPLIT; sp++)
        s += g_part[((size_t)sp*NPAD + n)*128 + l];
    out[1 + (size_t)n*NL + l] = s;
}

// ---------------- per-class S-PU risk -------------------------------------------
__global__ void k_risk(const float* __restrict__ out, const int* __restrict__ labels,
                       const float* __restrict__ pl, const float* __restrict__ po) {
    int r = blockIdx.x;
    int tid = threadIdx.x;
    float s_neg = 0.f, s_pp = 0.f, s_pn = 0.f, c_pos = 0.f;
    for (int n = tid; n < NTOT; n += 256) {
        float l0 = out[1 + (size_t)n*NL];
        float sc = out[1 + (size_t)n*NL + (r+1)] - l0;
        bool pos = labels[(size_t)n*NL + (r+1)] == 1;
        float lp = 0.25f * (sc - 1.f) * (sc - 1.f);
        float ln = 0.25f * (-sc - 1.f) * (-sc - 1.f);
        if (pos) { c_pos += 1.f; s_pp += lp; s_pn += ln; }
        else     { s_neg += ln; }
    }
    __shared__ float red[4][256];
    red[0][tid] = s_neg; red[1][tid] = s_pp; red[2][tid] = s_pn; red[3][tid] = c_pos;
    __syncthreads();
    for (int st = 128; st > 0; st >>= 1) {
        if (tid < st) {
#pragma unroll
            for (int q = 0; q < 4; q++) red[q][tid] += red[q][tid + st];
        }
        __syncthreads();
    }
    if (tid == 0) {
        float cp = red[3][0], cn = (float)NTOT - cp;
        float sq_neg = (cn > 0.f) ? red[0][0] / fmaxf(cn, 1.f) : 0.f;
        float sq_pp  = (cp > 0.f) ? red[1][0] / fmaxf(cp, 1.f) : 0.f;
        float sq_pn  = (cp > 0.f) ? red[2][0] / fmaxf(cp, 1.f) : 0.f;
        float o = po[r], lq = pl[r];
        float w  = sqrtf((1.f - o) / o);
        float pu = (o - lq) / (1.f - lq);
        float risk1 = (1.f - o)/(1.f - pu)*sq_neg - (pu - pu*o)/(1.f - pu)*sq_pn;
        float risk2 = o * sq_pp * w;
        g_riskc[r] = (risk1 < 0.f) ? -risk1 : (risk1 + risk2);
    }
}

// ---------------- sum class risks -> out[0] -------------------------------------
__global__ void k_risk_sum(float* __restrict__ out) {
    __shared__ float rr[128];
    int t = threadIdx.x;
    rr[t] = (t < RELSn) ? g_riskc[t] : 0.f;
    __syncthreads();
    for (int st = 64; st > 0; st >>= 1) {
        if (t < st) rr[t] += rr[t + st];
        __syncthreads();
    }
    if (t == 0) out[0] = rr[0];
}

// ---------------- launch ---------------------------------------------------------
extern "C" void kernel_launch(void* const* d_in, const int* in_sizes, int n_in,
                              void* d_out, int out_size) {
    const float* seq      = (const float*)d_in[0];
    const float* att      = (const float*)d_in[1];
    const int*   midx     = (const int*)  d_in[2];
    const float* mmask    = (const float*)d_in[3];
    const int*   hts      = (const int*)  d_in[4];
    const int*   labels   = (const int*)  d_in[5];
    const float* priors_l = (const float*)d_in[6];
    const float* priors_o = (const float*)d_in[7];
    const float* head_W   = (const float*)d_in[8];
    const float* head_b   = (const float*)d_in[9];
    const float* tail_W   = (const float*)d_in[10];
    const float* tail_b   = (const float*)d_in[11];
    const float* bil_W    = (const float*)d_in[12];
    const float* bil_b    = (const float*)d_in[13];
    float* out = (float*)d_out;

    cudaFuncSetAttribute(k_bilin_mma, cudaFuncAttributeMaxDynamicSharedMemorySize, SB_TOT);
    cudaFuncSetAttribute(k_rs_mma,  cudaFuncAttributeMaxDynamicSharedMemorySize, GEMM_SM);
    cudaFuncSetAttribute(k_rw_mma,  cudaFuncAttributeMaxDynamicSharedMemorySize, GEMM_SM);
    cudaFuncSetAttribute(k_c96,     cudaFuncAttributeMaxDynamicSharedMemorySize, C96_SM);

    k_wsplit<<<768, 256>>>(bil_W);
    k_wbsplit<<<(768*768 + 255)/256, 256>>>(head_W, tail_W);
    k_seqsplit<<<(Bq*Cc*384 + 255)/256, 256>>>(seq);
    k_ent_emb<<<Bq*Ee, 256>>>(seq, midx, mmask);
    k_ent_att<<<Bq*Ee*Hh, 256>>>(att, midx, mmask);
    k_ht<<<NTOT, 256>>>(hts);
    k_rs_mma<<<dim3(5, 6, 4), 256, GEMM_SM>>>();
    k_entU<<<dim3(2, 12, 2), 256>>>(head_W, tail_W);
    k_rw_mma<<<dim3(19, 12), 256, GEMM_SM>>>(hts, head_b, tail_b);
    k_bilin_mma<<<dim3(10, 12), 512, SB_TOT>>>();
    k_c96<<<dim3(19, 12), 128, C96_SM>>>();
    k_logits<<<(NTOT*NL + 255)/256, 256>>>(bil_b, out);
    k_risk<<<RELSn, 256>>>(out, labels, priors_l, priors_o);
    k_risk_sum<<<1, 128>>>(out);
}

// round 8
// speedup vs baseline: 2.7011x; 1.1493x over previous
#include <cuda_runtime.h>
#include <cuda_bf16.h>
#include <cuda_fp16.h>
#include <math.h>
#include <stdint.h>

#define Bq    4
#define Hh    12
#define Cc    1024
#define Dd    768
#define Ee    30
#define Mm    8
#define Pp    600
#define NL    97
#define RELSn 96
#define EMBn  768
#define NTOT  2400   // B*P
#define NPAD  2560   // 10 tiles of 256 (rows >= NTOT stay zero)
#define NSPLIT 12    // k blocks

// ---------------- scratch (static device globals; no allocation) -------------
__device__ float g_ent_emb[Bq*Ee*Dd];          // [B,E,D]
__device__ float g_ent_att[Bq*Ee*Hh*Cc];       // [B,E,H,C]
__device__ float g_hz[NPAD*EMBn];              // rows >=2400 stay zero
__device__ float g_tz[NPAD*EMBn];
__device__ uint32_t g_wtf[768*3072];           // bil W fp16 hi: [blob][64 j][48 lpair]
__device__ uint32_t g_wtl[768*3072];           // bil W fp16 lo (residual)
__device__ float    g_w96[768*64];             // bil W col 96: [blob][j]
__device__ uint32_t g_ht_hi[Bq*640*512];       // ht_att bf16 pairs [b][640][512]
__device__ uint32_t g_ht_lo[Bq*640*512];
__device__ uint32_t g_seq_hi[Bq*Cc*384];       // seq bf16 pairs [b][1024][384]
__device__ uint32_t g_seq_lo[Bq*Cc*384];
__device__ uint32_t g_rs_hi[2432*384];         // rs bf16 pairs (pad rows zero)
__device__ uint32_t g_rs_lo[2432*384];
__device__ uint32_t g_wb_hi[768*768];          // [W_bot_head | W_bot_tail] pairs
__device__ uint32_t g_wb_lo[768*768];
__device__ float g_U[2*Bq*Ee*EMBn];            // ent_emb @ W_top (head, tail)
__device__ float g_part[NSPLIT*NPAD*128];      // split partial logits
__device__ float g_riskc[RELSn];
__device__ unsigned int g_rdone = 0;

// =================== helpers ===================================================
__device__ __forceinline__ uint32_t smem_u32(const void* p) {
    uint32_t a;
    asm("{ .reg .u64 t; cvta.to.shared.u64 t, %1; cvt.u32.u64 %0, t; }" : "=r"(a) : "l"(p));
    return a;
}
__device__ __forceinline__ void pack2(float p0, float p1, uint32_t& hi, uint32_t& lo) {
    uint32_t h;
    asm("cvt.rn.bf16x2.f32 %0, %1, %2;" : "=r"(h) : "f"(p1), "f"(p0));
    float h0 = __uint_as_float(h << 16);
    float h1 = __uint_as_float(h & 0xFFFF0000u);
    float l0 = p0 - h0, l1 = p1 - h1;
    uint32_t l;
    asm("cvt.rn.bf16x2.f32 %0, %1, %2;" : "=r"(l) : "f"(l1), "f"(l0));
    hi = h; lo = l;
}
__device__ __forceinline__ void pack2h(float p0, float p1, uint32_t& hi, uint32_t& lo) {
    __half2 h = __floats2half2_rn(p0, p1);
    float2 hf = __half22float2(h);
    __half2 l = __floats2half2_rn(p0 - hf.x, p1 - hf.y);
    hi = *(uint32_t*)&h;
    lo = *(uint32_t*)&l;
}
__device__ __forceinline__ void ldm_x4(uint32_t* r, uint32_t addr) {
    asm volatile("ldmatrix.sync.aligned.m8n8.x4.shared.b16 {%0,%1,%2,%3}, [%4];"
        : "=r"(r[0]), "=r"(r[1]), "=r"(r[2]), "=r"(r[3]) : "r"(addr));
}
__device__ __forceinline__ void ldm_x4_t(uint32_t* r, uint32_t addr) {
    asm volatile("ldmatrix.sync.aligned.m8n8.x4.trans.shared.b16 {%0,%1,%2,%3}, [%4];"
        : "=r"(r[0]), "=r"(r[1]), "=r"(r[2]), "=r"(r[3]) : "r"(addr));
}
__device__ __forceinline__ void ldm_x2_t(uint32_t* r, uint32_t addr) {
    asm volatile("ldmatrix.sync.aligned.m8n8.x2.trans.shared.b16 {%0,%1}, [%2];"
        : "=r"(r[0]), "=r"(r[1]) : "r"(addr));
}
__device__ __forceinline__ void mma_bf16(float* d, const uint32_t* a, const uint32_t* b) {
    asm volatile(
        "mma.sync.aligned.m16n8k16.row.col.f32.bf16.bf16.f32 "
        "{%0,%1,%2,%3}, {%4,%5,%6,%7}, {%8,%9}, {%0,%1,%2,%3};"
        : "+f"(d[0]), "+f"(d[1]), "+f"(d[2]), "+f"(d[3])
        : "r"(a[0]), "r"(a[1]), "r"(a[2]), "r"(a[3]), "r"(b[0]), "r"(b[1]));
}
__device__ __forceinline__ void mma_f16(float* d, const uint32_t* a, const uint32_t* b) {
    asm volatile(
        "mma.sync.aligned.m16n8k16.row.col.f32.f16.f16.f32 "
        "{%0,%1,%2,%3}, {%4,%5,%6,%7}, {%8,%9}, {%0,%1,%2,%3};"
        : "+f"(d[0]), "+f"(d[1]), "+f"(d[2]), "+f"(d[3])
        : "r"(a[0]), "r"(a[1]), "r"(a[2]), "r"(a[3]), "r"(b[0]), "r"(b[1]));
}
#define CPASYNC(dst, src) asm volatile("cp.async.cg.shared.global [%0], [%1], 16;" :: "r"(dst), "l"(src))
#define CPCOMMIT()        asm volatile("cp.async.commit_group;")
#define CPWAIT(n)         asm volatile("cp.async.wait_group %0;" :: "n"(n) : "memory")

// ---------------- K_PREP: fused ent_att | wsplit | ent_emb | wbsplit | seqsplit -
// blocks: [0,1440) ent_att | [1440,2208) wsplit | [2208,2328) ent_emb
//         [2328,2904) wbsplit | [2904,4440) seqsplit
__global__ __launch_bounds__(256) void k_prep(
    const float* __restrict__ seq, const float* __restrict__ att,
    const int* __restrict__ midx, const float* __restrict__ mmask,
    const float* __restrict__ bilW,
    const float* __restrict__ hW, const float* __restrict__ tW)
{
    int bid = blockIdx.x;
    int tid = threadIdx.x;
    __shared__ int   s_idx[Mm];
    __shared__ float s_w[Mm];

    if (bid < 1440) {
        // ---- ent_att
        int g  = bid;
        int h  = g % Hh;
        int be = g / Hh;
        int b  = be / Ee;
        if (tid < Mm) {
            s_idx[tid] = midx[be*Mm + tid] + 1;
            s_w[tid]   = mmask[be*Mm + tid];
        }
        __syncthreads();
        float cnt = 0.f;
#pragma unroll
        for (int m = 0; m < Mm; m++) cnt += s_w[m];
        float inv = 1.f / cnt;
        const float* base = att + ((size_t)b*Hh + h)*Cc*Cc;
        for (int c = tid; c < Cc; c += 256) {
            float s = 0.f;
#pragma unroll
            for (int m = 0; m < Mm; m++)
                s += s_w[m] * base[(size_t)s_idx[m]*Cc + c];
            g_ent_att[(size_t)g*Cc + c] = s * inv;
        }
    } else if (bid < 2208) {
        // ---- wsplit: bil_W -> fp16 hi/lo cols [0,96) + fp32 col 96
        int blob = bid - 1440;
        int j = tid >> 2, lq = (tid & 3) * 24;
        size_t row = ((size_t)blob*64 + j) * NL;
        uint32_t* oh = g_wtf + ((size_t)blob*64 + j)*48 + (lq >> 1);
        uint32_t* ol = g_wtl + ((size_t)blob*64 + j)*48 + (lq >> 1);
#pragma unroll
        for (int q = 0; q < 12; q++) {
            int l0 = lq + q*2;
            float v0 = bilW[row + l0];
            float v1 = bilW[row + l0 + 1];
            uint32_t h, l;
            pack2h(v0, v1, h, l);
            oh[q] = h; ol[q] = l;
        }
        if ((tid & 3) == 0) g_w96[(size_t)blob*64 + j] = bilW[row + 96];
    } else if (bid < 2328) {
        // ---- ent_emb (weighted logsumexp)
        int be = bid - 2208;
        int b  = be / Ee;
        if (tid < Mm) {
            s_idx[tid] = midx[be*Mm + tid] + 1;
            s_w[tid]   = mmask[be*Mm + tid];
        }
        __syncthreads();
        for (int d = tid; d < Dd; d += 256) {
            float xv[Mm];
            float mx = -1e30f;
#pragma unroll
            for (int m = 0; m < Mm; m++) {
                float x = seq[((size_t)b*Cc + s_idx[m])*Dd + d];
                xv[m] = x;
                if (s_w[m] > 0.f) mx = fmaxf(mx, x);
            }
            float s = 0.f;
#pragma unroll
            for (int m = 0; m < Mm; m++)
                if (s_w[m] > 0.f) s += s_w[m] * __expf(xv[m] - mx);
            g_ent_emb[(size_t)be*Dd + d] = __logf(s) + mx;
        }
    } else if (bid < 2904) {
        // ---- wbsplit: 4 elems/thread; total 768*768
        int i0 = (bid - 2328)*1024 + tid*4;
#pragma unroll
        for (int q = 0; q < 4; q++) {
            int i = i0 + q;
            int kk = i / 768, c = i % 768;
            int c2 = c*2;
            const float* W = (c2 < 768) ? hW : tW;
            int col = (c2 < 768) ? c2 : (c2 - 768);
            size_t ro = (size_t)(768 + kk) * EMBn;
            uint32_t h, l;
            pack2(W[ro + col], W[ro + col + 1], h, l);
            g_wb_hi[i] = h; g_wb_lo[i] = l;
        }
    } else {
        // ---- seqsplit: 4 elems/thread; total 4*1024*384
        int i0 = (bid - 2904)*1024 + tid*4;
#pragma unroll
        for (int q = 0; q < 4; q++) {
            int i = i0 + q;
            uint32_t h, l;
            pack2(seq[(size_t)i*2], seq[(size_t)i*2+1], h, l);
            g_seq_hi[i] = h; g_seq_lo[i] = l;
        }
    }
}

// ---------------- K_HT: ht_att -> bf16 hi/lo split ------------------------------
__global__ void k_ht(const int* __restrict__ hts) {
    int n = blockIdx.x;
    int b = n / Pp, p = n % Pp;
    int hi = hts[n*2 + 0], ti = hts[n*2 + 1];
    size_t hb = (size_t)(b*Ee + hi) * Hh * Cc;
    size_t tb = (size_t)(b*Ee + ti) * Hh * Cc;
    __shared__ float vals[Cc];
    __shared__ float red[256];
    float loc = 0.f;
    for (int c = threadIdx.x; c < Cc; c += 256) {
        float s = 0.f;
#pragma unroll
        for (int h = 0; h < Hh; h++)
            s += g_ent_att[hb + (size_t)h*Cc + c] * g_ent_att[tb + (size_t)h*Cc + c];
        s *= (1.f / Hh);
        vals[c] = s;
        loc += s;
    }
    red[threadIdx.x] = loc;
    __syncthreads();
    for (int st = 128; st > 0; st >>= 1) {
        if (threadIdx.x < st) red[threadIdx.x] += red[threadIdx.x + st];
        __syncthreads();
    }
    float invt = 1.f / (red[0] + 1e-5f);
    uint32_t* oh = g_ht_hi + ((size_t)b*640 + p)*512;
    uint32_t* ol = g_ht_lo + ((size_t)b*640 + p)*512;
    for (int c2 = threadIdx.x; c2 < 512; c2 += 256) {
        float v0 = vals[c2*2]   * invt;
        float v1 = vals[c2*2+1] * invt;
        uint32_t h, l;
        pack2(v0, v1, h, l);
        oh[c2] = h; ol[c2] = l;
    }
}

// ---------------- bf16x3 mma GEMM mainloop (128x128 tile, 256 thr) -------------
#define GA_H 0
#define GA_L 18432
#define GB_H 36864
#define GB_L 54272
#define GEMM_SM 71680

__device__ __forceinline__ void gemm_main(float acc[4][4][4],
    const uint32_t* __restrict__ Ah, const uint32_t* __restrict__ Al,
    const uint32_t* __restrict__ Bh, const uint32_t* __restrict__ Bl,
    int K, int N, int m0, int n0)
{
    extern __shared__ char sm[];
    uint32_t smb = smem_u32(sm);
    int tid = threadIdx.x, lane = tid & 31, wid = tid >> 5;
    int lda32 = K >> 1, ldb32 = N >> 1;
    int wn = wid >> 2, wl = wid & 3, lq = lane & 15, lh = lane >> 4;
    uint32_t a_base  = smb + GA_H + (wn*64 + lq)*144 + lh*16;
    uint32_t al_base = a_base + (GA_L - GA_H);
    uint32_t b_base  = smb + GB_H + lq*272 + (wl*64 + lh*16);
    uint32_t bl_base = b_base + (GB_L - GB_H);
    for (int kc = 0; kc < K; kc += 64) {
#pragma unroll
        for (int rep = 0; rep < 4; rep++) {
            int idx = tid + rep*256;
            int row = idx >> 3, c4 = idx & 7;
            size_t go = (size_t)(m0 + row)*lda32 + (kc >> 1) + c4*4;
            *(uint4*)(sm + GA_H + row*144 + c4*16) = *(const uint4*)&Ah[go];
            *(uint4*)(sm + GA_L + row*144 + c4*16) = *(const uint4*)&Al[go];
        }
#pragma unroll
        for (int rep = 0; rep < 4; rep++) {
            int idx = tid + rep*256;
            int row = idx >> 4, c4 = idx & 15;
            size_t go = (size_t)(kc + row)*ldb32 + (n0 >> 1) + c4*4;
            *(uint4*)(sm + GB_H + row*272 + c4*16) = *(const uint4*)&Bh[go];
            *(uint4*)(sm + GB_L + row*272 + c4*16) = *(const uint4*)&Bl[go];
        }
        __syncthreads();
#pragma unroll
        for (int kt = 0; kt < 4; kt++) {
            uint32_t a_hi[4][4], a_lo[4][4];
#pragma unroll
            for (int mt = 0; mt < 4; mt++) {
                ldm_x4(a_hi[mt], a_base  + mt*2304 + kt*32);
                ldm_x4(a_lo[mt], al_base + mt*2304 + kt*32);
            }
#pragma unroll
            for (int lt = 0; lt < 2; lt++) {
                uint32_t b_hi[4], b_lo[4];
                ldm_x4_t(b_hi, b_base  + kt*4352 + lt*32);
                ldm_x4_t(b_lo, bl_base + kt*4352 + lt*32);
#pragma unroll
                for (int mt = 0; mt < 4; mt++) {
#pragma unroll
                    for (int f = 0; f < 2; f++) {
                        float* d = acc[mt][lt*2 + f];
                        mma_bf16(d, a_hi[mt], &b_hi[f*2]);
                        mma_bf16(d, a_lo[mt], &b_hi[f*2]);
                        mma_bf16(d, a_hi[mt], &b_lo[f*2]);
                    }
                }
            }
        }
        __syncthreads();
    }
}

// ---------------- K_RS_ENTU: fused rs GEMM (120 blocks) + entU (48 blocks) -----
__global__ __launch_bounds__(256, 2) void k_rs_entU(const float* __restrict__ hW,
                                                    const float* __restrict__ tW) {
    extern __shared__ char sm[];
    int bid = blockIdx.x;
    int tid = threadIdx.x;
    if (bid < 120) {
        // ---- rs = ht_att @ seq, epilogue -> bf16 hi/lo pairs
        int b = bid / 30;
        int rem = bid % 30;
        int m0 = (rem % 5) * 128, n0 = (rem / 5) * 128;
        float acc[4][4][4] = {};
        gemm_main(acc,
                  g_ht_hi + (size_t)b*640*512, g_ht_lo + (size_t)b*640*512,
                  g_seq_hi + (size_t)b*Cc*384, g_seq_lo + (size_t)b*Cc*384,
                  Cc, Dd, m0, n0);
        int lane = tid & 31, wid = tid >> 5;
        int wn = wid >> 2, wl = wid & 3;
        int rbase = m0 + wn*64 + (lane >> 2);
        int cbase = n0 + wl*32 + (lane & 3)*2;
#pragma unroll
        for (int mt = 0; mt < 4; mt++) {
#pragma unroll
            for (int lf = 0; lf < 4; lf++) {
                int r = rbase + mt*16;
                int cp = (cbase + lf*8) >> 1;
                float* d = acc[mt][lf];
                if (r < Pp) {
                    uint32_t h, l;
                    pack2(d[0], d[1], h, l);
                    g_rs_hi[((size_t)(b*Pp + r))*384 + cp] = h;
                    g_rs_lo[((size_t)(b*Pp + r))*384 + cp] = l;
                }
                if (r + 8 < Pp) {
                    uint32_t h, l;
                    pack2(d[2], d[3], h, l);
                    g_rs_hi[((size_t)(b*Pp + r + 8))*384 + cp] = h;
                    g_rs_lo[((size_t)(b*Pp + r + 8))*384 + cp] = l;
                }
            }
        }
    } else {
        // ---- entU: ent_emb @ W_top (SIMT)
        int idx = bid - 120;
        int mb = (idx & 1) * 64;
        int nb = ((idx >> 1) % 12) * 64;
        int s  = idx / 24;
        const float* W = s ? tW : hW;
        float* As = (float*)sm;             // [16][64]
        float* Bs = (float*)(sm + 4096);    // [16][64]
        int tm = tid >> 4, tn = tid & 15;
        int lm = tid & 63, lk4 = (tid >> 6) << 2;
        float acc[4][4] = {};
        for (int kc = 0; kc < Dd; kc += 16) {
            float4 av = make_float4(0.f,0.f,0.f,0.f);
            int m = mb + lm;
            if (m < Bq*Ee) av = *(const float4*)&g_ent_emb[(size_t)m*Dd + kc + lk4];
            As[(lk4+0)*64+lm] = av.x; As[(lk4+1)*64+lm] = av.y;
            As[(lk4+2)*64+lm] = av.z; As[(lk4+3)*64+lm] = av.w;
#pragma unroll
            for (int r = 0; r < 4; r++) {
                int kk = lk4 + r;
                Bs[kk*64+lm] = W[(size_t)(kc+kk)*EMBn + nb + lm];
            }
            __syncthreads();
#pragma unroll
            for (int kk = 0; kk < 16; kk++) {
                float4 a4 = *(const float4*)&As[kk*64 + tm*4];
                float4 b4 = *(const float4*)&Bs[kk*64 + tn*4];
                acc[0][0] += a4.x*b4.x; acc[0][1] += a4.x*b4.y; acc[0][2] += a4.x*b4.z; acc[0][3] += a4.x*b4.w;
                acc[1][0] += a4.y*b4.x; acc[1][1] += a4.y*b4.y; acc[1][2] += a4.y*b4.z; acc[1][3] += a4.y*b4.w;
                acc[2][0] += a4.z*b4.x; acc[2][1] += a4.z*b4.y; acc[2][2] += a4.z*b4.z; acc[2][3] += a4.z*b4.w;
                acc[3][0] += a4.w*b4.x; acc[3][1] += a4.w*b4.y; acc[3][2] += a4.w*b4.z; acc[3][3] += a4.w*b4.w;
            }
            __syncthreads();
        }
#pragma unroll
        for (int a = 0; a < 4; a++) {
            int m = mb + tm*4 + a;
            if (m < Bq*Ee)
                *(float4*)&g_U[((size_t)s*Bq*Ee + m)*EMBn + nb + tn*4] =
                    make_float4(acc[a][0], acc[a][1], acc[a][2], acc[a][3]);
        }
    }
}

// ---------------- K_RW: rs @ [Wbh|Wbt]; fused U-gather + bias + tanh ------------
__global__ __launch_bounds__(256, 2) void k_rw_mma(const int* __restrict__ hts,
                                                   const float* __restrict__ hb,
                                                   const float* __restrict__ tb) {
    int m0 = blockIdx.x * 128, n0 = blockIdx.y * 128;
    float acc[4][4][4] = {};
    gemm_main(acc, g_rs_hi, g_rs_lo, g_wb_hi, g_wb_lo, Dd, 1536, m0, n0);
    int tid = threadIdx.x, lane = tid & 31, wid = tid >> 5;
    int wn = wid >> 2, wl = wid & 3;
    int rbase = m0 + wn*64 + (lane >> 2);
    int cbase = n0 + wl*32 + (lane & 3)*2;
#pragma unroll
    for (int mt = 0; mt < 4; mt++) {
#pragma unroll
        for (int rr = 0; rr < 2; rr++) {
            int r = rbase + mt*16 + rr*8;
            if (r >= NTOT) continue;
            int b = r / Pp;
            int e0 = hts[r*2 + 0], e1 = hts[r*2 + 1];
#pragma unroll
            for (int lf = 0; lf < 4; lf++) {
                int c = cbase + lf*8;
                int s = (c >= 768);
                int cc = c - (s ? 768 : 0);
                int e = s ? e1 : e0;
                const float* Ur = g_U + ((size_t)(s*Bq*Ee + b*Ee + e))*EMBn + cc;
                const float* bi = (s ? tb : hb) + cc;
                float* dst = (s ? g_tz : g_hz) + (size_t)r*EMBn + cc;
                float* d = acc[mt][lf];
                float2 o;
                o.x = tanhf(d[rr*2 + 0] + Ur[0] + bi[0]);
                o.y = tanhf(d[rr*2 + 1] + Ur[1] + bi[1]);
                *(float2*)dst = o;
            }
        }
    }
}

// ---------------- K_BILIN_C96: fused fp16x3 bilinear (120) + col96 (228) -------
#define SB_TZ 0
#define SB_AH 65536
#define SB_AL 102400
#define SB_B0 139264
#define SB_BUF 26624     // hi 13312 + lo 13312 (64 rows x 208B)
#define SB_TOT 192512

__global__ __launch_bounds__(512, 1) void k_bilin_c96() {
    extern __shared__ char sm[];
    uint32_t smb = smem_u32(sm);
    int bid = blockIdx.x;
    int tid = threadIdx.x, lane = tid & 31, wid = tid >> 5;

    if (bid >= 120) {
        // ---- c96: exact fp32 column 96 (128-row tiles)
        int idx = bid - 120;
        int n0 = (idx % 19) * 128, k = idx / 19;
        float* Ws  = (float*)sm;          // [64][64]
        float* hzs = Ws + 4096;           // [128][65]
        float* tzs = hzs + 128*65;        // [128][65]
        for (int e = tid; e < 4096; e += 512)
            Ws[e] = g_w96[(size_t)k*4096 + e];
        for (int e = tid; e < 128*64; e += 512) {
            int r = e >> 6, c = e & 63;
            int n = n0 + r;
            float hv = 0.f, tv = 0.f;
            if (n < NTOT) {
                hv = g_hz[(size_t)n*EMBn + k*64 + c];
                tv = g_tz[(size_t)n*EMBn + k*64 + c];
            }
            hzs[r*65 + c] = hv;
            tzs[r*65 + c] = tv;
        }
        __syncthreads();
        if (tid < 128) {
            float tzr[64];
#pragma unroll
            for (int j = 0; j < 64; j++) tzr[j] = tzs[tid*65 + j];
            float acc = 0.f;
            for (int i = 0; i < 64; i++) {
                const float4* wr = (const float4*)&Ws[i*64];
                float s = 0.f;
#pragma unroll
                for (int j4 = 0; j4 < 16; j4++) {
                    float4 w = wr[j4];
                    s += w.x*tzr[j4*4] + w.y*tzr[j4*4+1] + w.z*tzr[j4*4+2] + w.w*tzr[j4*4+3];
                }
                acc += hzs[tid*65 + i] * s;
            }
            int n = n0 + tid;
            if (n < NTOT) g_part[((size_t)k*NPAD + n)*128 + 96] = acc;
        }
        return;
    }

    // ---- bilinear
    float* TZ = (float*)(sm + SB_TZ);
    int n0 = (bid % 10) * 256, k = bid / 10;

    for (int idx = tid; idx < 4096; idx += 512) {
        int r = idx >> 4, c = (idx & 15) * 4;
        *(float4*)&TZ[r*64 + c] = *(const float4*)&g_tz[(size_t)(n0 + r)*EMBn + k*64 + c];
    }
    int anl = tid >> 1, ajh = tid & 1;
    const float* hzp = g_hz + (size_t)(n0 + anl)*EMBn + k*64;
    int wn = wid >> 2, wl = wid & 3;
    int lq = lane & 15, lh = lane >> 4;
    uint32_t a_base  = smb + SB_AH + (wn*64 + lq)*144 + lh*16;
    uint32_t al_base = a_base + (SB_AL - SB_AH);
    uint32_t b_off4  = lq*208 + wl*48 + lh*16;
    uint32_t b_off2  = (lane & 15)*208 + wl*48 + 32;

    {
        const uint4* srch = ((const uint4*)g_wtf) + (size_t)(k*64)*768;
        const uint4* srcl = ((const uint4*)g_wtl) + (size_t)(k*64)*768;
        int idx = tid;
        if (idx < 768) {
            int j = idx / 12, c = idx % 12;
            CPASYNC(smb + SB_B0 + j*208 + c*16, srch + idx);
            CPASYNC(smb + SB_B0 + 13312 + j*208 + c*16, srcl + idx);
        }
        idx = tid + 512;
        if (idx < 768) {
            int j = idx / 12, c = idx % 12;
            CPASYNC(smb + SB_B0 + j*208 + c*16, srch + idx);
            CPASYNC(smb + SB_B0 + 13312 + j*208 + c*16, srcl + idx);
        }
        CPCOMMIT();
    }

    float acc[4][3][4] = {};
    __syncthreads();

    for (int i = 0; i < 64; i++) {
        if (i < 63) {
            size_t blob = (size_t)(k*64 + i + 1) * 768;
            const uint4* srch = ((const uint4*)g_wtf) + blob;
            const uint4* srcl = ((const uint4*)g_wtl) + blob;
            uint32_t dst = smb + SB_B0 + ((i + 1) & 1) * SB_BUF;
            int idx = tid;
            if (idx < 768) {
                int j = idx / 12, c = idx % 12;
                CPASYNC(dst + j*208 + c*16, srch + idx);
                CPASYNC(dst + 13312 + j*208 + c*16, srcl + idx);
            }
            idx = tid + 512;
            if (idx < 768) {
                int j = idx / 12, c = idx % 12;
                CPASYNC(dst + j*208 + c*16, srch + idx);
                CPASYNC(dst + 13312 + j*208 + c*16, srcl + idx);
            }
            CPCOMMIT();
        }
        float hzv = hzp[i];
        const float* tzr = &TZ[anl*64 + ajh*32];
        char* ah = sm + SB_AH + anl*144 + ajh*64;
        char* al = sm + SB_AL + anl*144 + ajh*64;
#pragma unroll
        for (int g = 0; g < 4; g++) {
            float4 t0 = *(const float4*)&tzr[g*8];
            float4 t1 = *(const float4*)&tzr[g*8 + 4];
            uint32_t h[4], l[4];
            pack2h(hzv*t0.x, hzv*t0.y, h[0], l[0]);
            pack2h(hzv*t0.z, hzv*t0.w, h[1], l[1]);
            pack2h(hzv*t1.x, hzv*t1.y, h[2], l[2]);
            pack2h(hzv*t1.z, hzv*t1.w, h[3], l[3]);
            *(uint4*)(ah + g*16) = make_uint4(h[0], h[1], h[2], h[3]);
            *(uint4*)(al + g*16) = make_uint4(l[0], l[1], l[2], l[3]);
        }
        if (i < 63) { CPWAIT(1); } else { CPWAIT(0); }
        __syncthreads();
        uint32_t bhi = smb + SB_B0 + (i & 1) * SB_BUF;
        uint32_t blo = bhi + 13312;
#pragma unroll
        for (int kt = 0; kt < 4; kt++) {
            uint32_t bh4[4], bl4[4], bh2[2], bl2[2];
            ldm_x4_t(bh4, bhi + b_off4 + kt*3328);
            ldm_x2_t(bh2, bhi + b_off2 + kt*3328);
            ldm_x4_t(bl4, blo + b_off4 + kt*3328);
            ldm_x2_t(bl2, blo + b_off2 + kt*3328);
#pragma unroll
            for (int mt = 0; mt < 4; mt++) {
                uint32_t a_hi[4], a_lo[4];
                ldm_x4(a_hi, a_base  + mt*2304 + kt*32);
                ldm_x4(a_lo, al_base + mt*2304 + kt*32);
#pragma unroll
                for (int nf = 0; nf < 2; nf++) {
                    float* d = acc[mt][nf];
                    mma_f16(d, a_hi, &bh4[nf*2]);
                    mma_f16(d, a_lo, &bh4[nf*2]);
                    mma_f16(d, a_hi, &bl4[nf*2]);
                }
                float* d2 = acc[mt][2];
                mma_f16(d2, a_hi, bh2);
                mma_f16(d2, a_lo, bh2);
                mma_f16(d2, a_hi, bl2);
            }
        }
        __syncthreads();
    }
    int rbase = n0 + wn*64 + (lane >> 2);
    int cbase = wl*24 + (lane & 3)*2;
#pragma unroll
    for (int mt = 0; mt < 4; mt++) {
#pragma unroll
        for (int lf = 0; lf < 3; lf++) {
            int r = rbase + mt*16;
            int c = cbase + lf*8;
            float* d = acc[mt][lf];
            *(float2*)&g_part[((size_t)k*NPAD + r)*128 + c]     = make_float2(d[0], d[1]);
            *(float2*)&g_part[((size_t)k*NPAD + r + 8)*128 + c] = make_float2(d[2], d[3]);
        }
    }
}

// ---------------- reduce split partials + bias -> logits -----------------------
__global__ void k_logits(const float* __restrict__ bb, float* __restrict__ out) {
    int g = blockIdx.x * 256 + threadIdx.x;
    if (g >= NTOT*NL) return;
    int n = g / NL, l = g % NL;
    float s = bb[l];
#pragma unroll
    for (int sp = 0; sp < NSPLIT; sp++)
        s += g_part[((size_t)sp*NPAD + n)*128 + l];
    out[1 + (size_t)n*NL + l] = s;
}

// ---------------- K_RISK_ALL: per-class risk + last-block total -----------------
__global__ void k_risk_all(const float* __restrict__ out_ro, const int* __restrict__ labels,
                           const float* __restrict__ pl, const float* __restrict__ po,
                           float* __restrict__ out) {
    int r = blockIdx.x;
    int tid = threadIdx.x;
    float s_neg = 0.f, s_pp = 0.f, s_pn = 0.f, c_pos = 0.f;
    for (int n = tid; n < NTOT; n += 256) {
        float l0 = out_ro[1 + (size_t)n*NL];
        float sc = out_ro[1 + (size_t)n*NL + (r+1)] - l0;
        bool pos = labels[(size_t)n*NL + (r+1)] == 1;
        float lp = 0.25f * (sc - 1.f) * (sc - 1.f);
        float ln = 0.25f * (-sc - 1.f) * (-sc - 1.f);
        if (pos) { c_pos += 1.f; s_pp += lp; s_pn += ln; }
        else     { s_neg += ln; }
    }
    __shared__ float red[4][256];
    red[0][tid] = s_neg; red[1][tid] = s_pp; red[2][tid] = s_pn; red[3][tid] = c_pos;
    __syncthreads();
    for (int st = 128; st > 0; st >>= 1) {
        if (tid < st) {
#pragma unroll
            for (int q = 0; q < 4; q++) red[q][tid] += red[q][tid + st];
        }
        __syncthreads();
    }
    __shared__ unsigned int s_last;
    if (tid == 0) {
        float cp = red[3][0], cn = (float)NTOT - cp;
        float sq_neg = (cn > 0.f) ? red[0][0] / fmaxf(cn, 1.f) : 0.f;
        float sq_pp  = (cp > 0.f) ? red[1][0] / fmaxf(cp, 1.f) : 0.f;
        float sq_pn  = (cp > 0.f) ? red[2][0] / fmaxf(cp, 1.f) : 0.f;
        float o = po[r], lq = pl[r];
        float w  = sqrtf((1.f - o) / o);
        float pu = (o - lq) / (1.f - lq);
        float risk1 = (1.f - o)/(1.f - pu)*sq_neg - (pu - pu*o)/(1.f - pu)*sq_pn;
        float risk2 = o * sq_pp * w;
        g_riskc[r] = (risk1 < 0.f) ? -risk1 : (risk1 + risk2);
        __threadfence();
        s_last = atomicAdd(&g_rdone, 1u);
    }
    __syncthreads();
    if (s_last == RELSn - 1) {
        __threadfence();
        __shared__ float rr[128];
        if (tid < 128) rr[tid] = (tid < RELSn) ? g_riskc[tid] : 0.f;
        __syncthreads();
        for (int st = 64; st > 0; st >>= 1) {
            if (tid < st) rr[tid] += rr[tid + st];
            __syncthreads();
        }
        if (tid == 0) { out[0] = rr[0]; g_rdone = 0; }
    }
}

// ---------------- launch ---------------------------------------------------------
extern "C" void kernel_launch(void* const* d_in, const int* in_sizes, int n_in,
                              void* d_out, int out_size) {
    const float* seq      = (const float*)d_in[0];
    const float* att      = (const float*)d_in[1];
    const int*   midx     = (const int*)  d_in[2];
    const float* mmask    = (const float*)d_in[3];
    const int*   hts      = (const int*)  d_in[4];
    const int*   labels   = (const int*)  d_in[5];
    const float* priors_l = (const float*)d_in[6];
    const float* priors_o = (const float*)d_in[7];
    const float* head_W   = (const float*)d_in[8];
    const float* head_b   = (const float*)d_in[9];
    const float* tail_W   = (const float*)d_in[10];
    const float* tail_b   = (const float*)d_in[11];
    const float* bil_W    = (const float*)d_in[12];
    const float* bil_b    = (const float*)d_in[13];
    float* out = (float*)d_out;

    cudaFuncSetAttribute(k_bilin_c96, cudaFuncAttributeMaxDynamicSharedMemorySize, SB_TOT);
    cudaFuncSetAttribute(k_rs_entU,   cudaFuncAttributeMaxDynamicSharedMemorySize, GEMM_SM);
    cudaFuncSetAttribute(k_rw_mma,    cudaFuncAttributeMaxDynamicSharedMemorySize, GEMM_SM);

    k_prep<<<4440, 256>>>(seq, att, midx, mmask, bil_W, head_W, tail_W);
    k_ht<<<NTOT, 256>>>(hts);
    k_rs_entU<<<168, 256, GEMM_SM>>>(head_W, tail_W);
    k_rw_mma<<<dim3(19, 12), 256, GEMM_SM>>>(hts, head_b, tail_b);
    k_bilin_c96<<<348, 512, SB_TOT>>>();
    k_logits<<<(NTOT*NL + 255)/256, 256>>>(bil_b, out);
    k_risk_all<<<RELSn, 256>>>(out, labels, priors_l, priors_o, out);
}